// round 1
// baseline (speedup 1.0000x reference)
#include <cuda_runtime.h>

#define NN 10000
#define NE 160000
#define F 512
#define F4 128   // float4 per feature row

// ---------------- scratch (device globals: no allocation allowed) ----------
__device__ int   g_deg_out[NN];
__device__ int   g_deg_in[NN];
__device__ float g_norm_out[NN];
__device__ float g_norm_in[NN];
__device__ int   g_off[NN + 1];
__device__ int   g_cnt[NN];
__device__ int   g_csr_src[NE];
__device__ float g_csr_w[NE];
__device__ float g_agg[(size_t)NN * F];
__device__ float g_h1[(size_t)NN * F];

// ---------------- small setup kernels ---------------------------------------
__global__ void zero_kernel() {
    int i = blockIdx.x * blockDim.x + threadIdx.x;
    if (i < NN) { g_deg_out[i] = 0; g_deg_in[i] = 0; g_cnt[i] = 0; }
}

__global__ void degree_kernel(const int* __restrict__ src, const int* __restrict__ dst) {
    int e = blockIdx.x * blockDim.x + threadIdx.x;
    if (e < NE) {
        atomicAdd(&g_deg_out[src[e]], 1);
        atomicAdd(&g_deg_in[dst[e]], 1);
    }
}

__global__ void norm_kernel() {
    int i = blockIdx.x * blockDim.x + threadIdx.x;
    if (i < NN) {
        int dо = g_deg_out[i];
        int di = g_deg_in[i];
        g_norm_out[i] = dо > 0 ? rsqrtf((float)dо) : 0.f;
        g_norm_in[i]  = di > 0 ? rsqrtf((float)di) : 0.f;
    }
}

// single-block exclusive scan of g_deg_in -> g_off (10000 elems, 1024 threads)
__global__ void scan_kernel() {
    __shared__ int sh[32];
    __shared__ int s_carry;
    int tid = threadIdx.x;
    if (tid == 0) s_carry = 0;
    __syncthreads();
    for (int base = 0; base < NN; base += 1024) {
        int i = base + tid;
        int v = (i < NN) ? g_deg_in[i] : 0;
        int x = v;
        #pragma unroll
        for (int d = 1; d < 32; d <<= 1) {
            int y = __shfl_up_sync(0xffffffffu, x, d);
            if ((tid & 31) >= d) x += y;
        }
        if ((tid & 31) == 31) sh[tid >> 5] = x;
        __syncthreads();
        if (tid < 32) {
            int w = sh[tid];
            #pragma unroll
            for (int d = 1; d < 32; d <<= 1) {
                int y = __shfl_up_sync(0xffffffffu, w, d);
                if (tid >= d) w += y;
            }
            sh[tid] = w;
        }
        __syncthreads();
        int pref = (tid >= 32) ? sh[(tid >> 5) - 1] : 0;
        int incl = s_carry + pref + x;
        if (i < NN) g_off[i] = incl - v;   // exclusive
        __syncthreads();
        if (tid == 1023) s_carry = incl;
        __syncthreads();
    }
    if (tid == 0) g_off[NN] = s_carry;
}

__global__ void scatter_kernel(const int* __restrict__ src, const int* __restrict__ dst) {
    int e = blockIdx.x * blockDim.x + threadIdx.x;
    if (e < NE) {
        int d = dst[e];
        int pos = g_off[d] + atomicAdd(&g_cnt[d], 1);
        int s = src[e];
        g_csr_src[pos] = s;
        g_csr_w[pos]   = g_norm_out[s];
    }
}

// ---------------- aggregation: one CTA per dst node -------------------------
// out[node] = norm_in[node] * sum_{e in in(node)} norm_out[src_e] * x[src_e]
__global__ __launch_bounds__(128) void agg_kernel(const float* __restrict__ x,
                                                  float* __restrict__ out) {
    int node = blockIdx.x;
    int tid  = threadIdx.x;
    int beg = g_off[node];
    int end = g_off[node + 1];
    const float4* x4 = reinterpret_cast<const float4*>(x);
    float4 acc = make_float4(0.f, 0.f, 0.f, 0.f);
    for (int i = beg; i < end; ++i) {
        int   s = __ldg(&g_csr_src[i]);
        float w = __ldg(&g_csr_w[i]);
        float4 v = x4[(size_t)s * F4 + tid];
        acc.x = fmaf(w, v.x, acc.x);
        acc.y = fmaf(w, v.y, acc.y);
        acc.z = fmaf(w, v.z, acc.z);
        acc.w = fmaf(w, v.w, acc.w);
    }
    float ni = g_norm_in[node];
    float4 r = make_float4(acc.x * ni, acc.y * ni, acc.z * ni, acc.w * ni);
    reinterpret_cast<float4*>(out)[(size_t)node * F4 + tid] = r;
}

// ---------------- SGEMM with fused bias (+optional ReLU) --------------------
// C[M,512] = A[M,512] @ B[512,512] + bias ; all row-major fp32
__global__ __launch_bounds__(256) void sgemm_bias_act(
    const float* __restrict__ A, const float* __restrict__ Bm,
    const float* __restrict__ bias, float* __restrict__ C,
    int M, int do_relu)
{
    constexpr int BM = 128, BN = 128, BK = 8, TM = 8, TN = 8;
    constexpr int Nn = 512, K = 512;
    __shared__ float As[BK][BM];
    __shared__ float Bs[BK][BN];

    int tid = threadIdx.x;
    int tx = tid & 15;     // 16 thread cols * TN=8 -> 128
    int ty = tid >> 4;     // 16 thread rows * TM=8 -> 128
    int bn = blockIdx.x * BN;
    int bm = blockIdx.y * BM;

    float acc[TM][TN];
    #pragma unroll
    for (int i = 0; i < TM; ++i)
        #pragma unroll
        for (int j = 0; j < TN; ++j) acc[i][j] = 0.f;

    int aRow = tid >> 1;          // 0..127
    int aCol = (tid & 1) * 4;     // 0 or 4
    int bRow = tid >> 5;          // 0..7
    int bCol = (tid & 31) * 4;    // 0..124

    for (int k0 = 0; k0 < K; k0 += BK) {
        float4 a = make_float4(0.f, 0.f, 0.f, 0.f);
        int gm = bm + aRow;
        if (gm < M)
            a = *reinterpret_cast<const float4*>(A + (size_t)gm * K + k0 + aCol);
        As[aCol + 0][aRow] = a.x;
        As[aCol + 1][aRow] = a.y;
        As[aCol + 2][aRow] = a.z;
        As[aCol + 3][aRow] = a.w;

        float4 b = *reinterpret_cast<const float4*>(Bm + (size_t)(k0 + bRow) * Nn + bn + bCol);
        *reinterpret_cast<float4*>(&Bs[bRow][bCol]) = b;
        __syncthreads();

        #pragma unroll
        for (int k = 0; k < BK; ++k) {
            float ar[TM], br[TN];
            #pragma unroll
            for (int i = 0; i < TM; i += 4)
                *reinterpret_cast<float4*>(&ar[i]) =
                    *reinterpret_cast<const float4*>(&As[k][ty * TM + i]);
            #pragma unroll
            for (int j = 0; j < TN; j += 4)
                *reinterpret_cast<float4*>(&br[j]) =
                    *reinterpret_cast<const float4*>(&Bs[k][tx * TN + j]);
            #pragma unroll
            for (int i = 0; i < TM; ++i)
                #pragma unroll
                for (int j = 0; j < TN; ++j)
                    acc[i][j] = fmaf(ar[i], br[j], acc[i][j]);
        }
        __syncthreads();
    }

    #pragma unroll
    for (int i = 0; i < TM; ++i) {
        int m = bm + ty * TM + i;
        if (m >= M) break;
        #pragma unroll
        for (int j = 0; j < TN; j += 4) {
            int n = bn + tx * TN + j;
            float4 r;
            r.x = acc[i][j + 0] + bias[n + 0];
            r.y = acc[i][j + 1] + bias[n + 1];
            r.z = acc[i][j + 2] + bias[n + 2];
            r.w = acc[i][j + 3] + bias[n + 3];
            if (do_relu) {
                r.x = fmaxf(r.x, 0.f);
                r.y = fmaxf(r.y, 0.f);
                r.z = fmaxf(r.z, 0.f);
                r.w = fmaxf(r.w, 0.f);
            }
            *reinterpret_cast<float4*>(C + (size_t)m * Nn + n) = r;
        }
    }
}

// ---------------- launcher ---------------------------------------------------
extern "C" void kernel_launch(void* const* d_in, const int* in_sizes, int n_in,
                              void* d_out, int out_size) {
    const float* x   = (const float*)d_in[0];
    const float* W1  = (const float*)d_in[1];
    const float* b1  = (const float*)d_in[2];
    const float* W2  = (const float*)d_in[3];
    const float* b2  = (const float*)d_in[4];
    const float* W3  = (const float*)d_in[5];
    const float* b3  = (const float*)d_in[6];
    const int*   src = (const int*)d_in[7];
    const int*   dst = (const int*)d_in[8];

    float* out = (float*)d_out;
    float* h4  = out;                         // layer-4 output (no relu)
    float* h3  = out + (size_t)NN * F;        // relu
    float* h2  = out + 2 * (size_t)NN * F;    // relu

    float* agg = nullptr;
    float* h1  = nullptr;
    cudaGetSymbolAddress((void**)&agg, g_agg);
    cudaGetSymbolAddress((void**)&h1,  g_h1);

    const int TB = 256;
    zero_kernel<<<(NN + TB - 1) / TB, TB>>>();
    degree_kernel<<<(NE + TB - 1) / TB, TB>>>(src, dst);
    norm_kernel<<<(NN + TB - 1) / TB, TB>>>();
    scan_kernel<<<1, 1024>>>();
    scatter_kernel<<<(NE + TB - 1) / TB, TB>>>(src, dst);

    dim3 ggrid(4, (NN + 127) / 128);   // N=512/128, ceil(M/128)

    // layer 1: h1 = relu(agg(x) @ W1 + b1)
    agg_kernel<<<NN, 128>>>(x, agg);
    sgemm_bias_act<<<ggrid, 256>>>(agg, W1, b1, h1, NN, 1);

    // layer 2: h2 = relu(agg(h1) @ W2 + b2)
    agg_kernel<<<NN, 128>>>(h1, agg);
    sgemm_bias_act<<<ggrid, 256>>>(agg, W2, b2, h2, NN, 1);

    // shared aggregation of h2 feeds both h3 and h4
    agg_kernel<<<NN, 128>>>(h2, agg);
    sgemm_bias_act<<<ggrid, 256>>>(agg, W2, b2, h3, NN, 1);  // h3 = relu(. @ W2 + b2)
    sgemm_bias_act<<<ggrid, 256>>>(agg, W3, b3, h4, NN, 0);  // h4 = . @ W3 + b3
}

// round 3
// speedup vs baseline: 2.8540x; 2.8540x over previous
#include <cuda_runtime.h>
#include <cuda_bf16.h>
#include <cstdint>

#define NN 10000
#define NE 160000
#define F 512
#define F4 128

// ==================== scratch (device globals) ====================
__device__ int   g_deg_out[NN];
__device__ int   g_deg_in[NN];
__device__ float g_norm_out[NN];
__device__ float g_norm_in[NN];
__device__ int   g_off[NN + 1];
__device__ int   g_cnt[NN];
__device__ int   g_csr_src[NE];
__device__ float g_csr_w[NE];
__device__ float g_h1[(size_t)NN * F];
__device__ __nv_bfloat16 g_Ahi[(size_t)NN * F];
__device__ __nv_bfloat16 g_Alo[(size_t)NN * F];
__device__ __nv_bfloat16 g_W1hi[F * F], g_W1lo[F * F];
__device__ __nv_bfloat16 g_W2hi[F * F], g_W2lo[F * F];
__device__ __nv_bfloat16 g_W3hi[F * F], g_W3lo[F * F];

// ==================== PTX helpers (sm_80+ features only) ====================
__device__ __forceinline__ uint32_t smem_to_u32(const void* p) {
    uint32_t a;
    asm("{ .reg .u64 t; cvta.to.shared.u64 t, %1; cvt.u32.u64 %0, t; }" : "=r"(a) : "l"(p));
    return a;
}
__device__ __forceinline__ void cp_async16(uint32_t dst, const void* src, int sz) {
    asm volatile("cp.async.cg.shared.global [%0], [%1], 16, %2;"
        :: "r"(dst), "l"(src), "r"(sz) : "memory");
}
__device__ __forceinline__ void ldsm4(uint32_t* r, uint32_t addr) {
    asm volatile("ldmatrix.sync.aligned.m8n8.x4.shared.b16 {%0,%1,%2,%3}, [%4];"
        : "=r"(r[0]), "=r"(r[1]), "=r"(r[2]), "=r"(r[3]) : "r"(addr));
}
__device__ __forceinline__ void mma_bf16(float* d, const uint32_t* a, const uint32_t* b) {
    asm volatile(
        "mma.sync.aligned.m16n8k16.row.col.f32.bf16.bf16.f32 "
        "{%0,%1,%2,%3}, {%4,%5,%6,%7}, {%8,%9}, {%0,%1,%2,%3};"
        : "+f"(d[0]), "+f"(d[1]), "+f"(d[2]), "+f"(d[3])
        : "r"(a[0]), "r"(a[1]), "r"(a[2]), "r"(a[3]), "r"(b[0]), "r"(b[1]));
}

// ==================== setup kernels ====================
__global__ void zero_kernel() {
    int i = blockIdx.x * blockDim.x + threadIdx.x;
    if (i < NN) { g_deg_out[i] = 0; g_deg_in[i] = 0; g_cnt[i] = 0; }
}

__global__ void degree_kernel(const int* __restrict__ src, const int* __restrict__ dst) {
    int e = blockIdx.x * blockDim.x + threadIdx.x;
    if (e < NE) {
        atomicAdd(&g_deg_out[src[e]], 1);
        atomicAdd(&g_deg_in[dst[e]], 1);
    }
}

__global__ void norm_kernel() {
    int i = blockIdx.x * blockDim.x + threadIdx.x;
    if (i < NN) {
        int a = g_deg_out[i];
        int b = g_deg_in[i];
        g_norm_out[i] = a > 0 ? rsqrtf((float)a) : 0.f;
        g_norm_in[i]  = b > 0 ? rsqrtf((float)b) : 0.f;
    }
}

// exclusive scan of g_deg_in -> g_off; 1024 threads, 10 elems each, one pass
__global__ void scan_kernel() {
    __shared__ int wsum[32];
    int tid = threadIdx.x;
    int base = tid * 10;
    int loc[10];
    int s = 0;
    #pragma unroll
    for (int i = 0; i < 10; ++i) {
        loc[i] = s;
        int idx = base + i;
        s += (idx < NN) ? g_deg_in[idx] : 0;
    }
    int x = s;
    #pragma unroll
    for (int d = 1; d < 32; d <<= 1) {
        int y = __shfl_up_sync(0xffffffffu, x, d);
        if ((tid & 31) >= d) x += y;
    }
    if ((tid & 31) == 31) wsum[tid >> 5] = x;
    __syncthreads();
    if (tid < 32) {
        int w = wsum[tid];
        #pragma unroll
        for (int d = 1; d < 32; d <<= 1) {
            int y = __shfl_up_sync(0xffffffffu, w, d);
            if (tid >= d) w += y;
        }
        wsum[tid] = w;
    }
    __syncthreads();
    int pref = x - s + ((tid >= 32) ? wsum[(tid >> 5) - 1] : 0);
    #pragma unroll
    for (int i = 0; i < 10; ++i) {
        int idx = base + i;
        if (idx < NN) g_off[idx] = pref + loc[i];
    }
    if (tid == 1023) g_off[NN] = pref + s;
}

__global__ void scatter_kernel(const int* __restrict__ src, const int* __restrict__ dst) {
    int e = blockIdx.x * blockDim.x + threadIdx.x;
    if (e < NE) {
        int d = dst[e];
        int pos = g_off[d] + atomicAdd(&g_cnt[d], 1);
        int s = src[e];
        g_csr_src[pos] = s;
        g_csr_w[pos]   = g_norm_out[s];
    }
}

// W [512,512] (k-major) -> transposed hi/lo bf16 Wt[n][k]
__global__ void wsplit_kernel(const float* __restrict__ W,
                              __nv_bfloat16* __restrict__ Oh,
                              __nv_bfloat16* __restrict__ Ol) {
    __shared__ float t[32][33];
    int n = blockIdx.x * 32 + threadIdx.x;
    int k = blockIdx.y * 32 + threadIdx.y;
    t[threadIdx.y][threadIdx.x] = W[(size_t)k * F + n];
    __syncthreads();
    int on = blockIdx.x * 32 + threadIdx.y;
    int ok = blockIdx.y * 32 + threadIdx.x;
    float v = t[threadIdx.x][threadIdx.y];
    __nv_bfloat16 h = __float2bfloat16(v);
    Oh[(size_t)on * F + ok] = h;
    Ol[(size_t)on * F + ok] = __float2bfloat16(v - __bfloat162float(h));
}

// ==================== aggregation: one CTA per dst node ====================
__global__ __launch_bounds__(128) void agg_kernel(const float* __restrict__ x,
                                                  __nv_bfloat16* __restrict__ ohi,
                                                  __nv_bfloat16* __restrict__ olo) {
    int node = blockIdx.x;
    int tid  = threadIdx.x;
    int beg = g_off[node];
    int end = g_off[node + 1];
    const float4* x4 = reinterpret_cast<const float4*>(x);
    float4 acc = make_float4(0.f, 0.f, 0.f, 0.f);
    for (int i = beg; i < end; ++i) {
        int   s = __ldg(&g_csr_src[i]);
        float w = __ldg(&g_csr_w[i]);
        float4 v = x4[(size_t)s * F4 + tid];
        acc.x = fmaf(w, v.x, acc.x);
        acc.y = fmaf(w, v.y, acc.y);
        acc.z = fmaf(w, v.z, acc.z);
        acc.w = fmaf(w, v.w, acc.w);
    }
    float ni = g_norm_in[node];
    float r[4] = {acc.x * ni, acc.y * ni, acc.z * ni, acc.w * ni};
    unsigned short hb[4], lb[4];
    #pragma unroll
    for (int j = 0; j < 4; ++j) {
        __nv_bfloat16 h = __float2bfloat16(r[j]);
        float hf = __bfloat162float(h);
        __nv_bfloat16 l = __float2bfloat16(r[j] - hf);
        hb[j] = __bfloat16_as_ushort(h);
        lb[j] = __bfloat16_as_ushort(l);
    }
    uint2 uh = make_uint2((uint32_t)hb[0] | ((uint32_t)hb[1] << 16),
                          (uint32_t)hb[2] | ((uint32_t)hb[3] << 16));
    uint2 ul = make_uint2((uint32_t)lb[0] | ((uint32_t)lb[1] << 16),
                          (uint32_t)lb[2] | ((uint32_t)lb[3] << 16));
    reinterpret_cast<uint2*>(ohi + (size_t)node * F)[tid] = uh;
    reinterpret_cast<uint2*>(olo + (size_t)node * F)[tid] = ul;
}

// ==================== mma.sync GEMM: C = (Ah+Al)@(Bh+Bl)^T + bias ====================
// A: [M,512] bf16 hi/lo row-major. B: [512,512] bf16 hi/lo n-major (Bt[n][k]).
// CTA tile 128x128, BK=32, cp.async double buffer.
// Stage layout (32KB): Ah[0..8K) Al[8K..16K) Bh[16K..24K) Bl[24K..32K)
// Tile storage: 128 rows x 64B (4 x 16B chunks), chunk ^= (row>>1)&3 swizzle.
#define STAGE_BYTES 32768
#define GEMM_SMEM (2 * STAGE_BYTES)

__device__ __forceinline__ void load_stage(
    uint32_t s, int m0, int n0, int M, int k0, int tid,
    const __nv_bfloat16* __restrict__ Ah, const __nv_bfloat16* __restrict__ Al,
    const __nv_bfloat16* __restrict__ Bh, const __nv_bfloat16* __restrict__ Bl)
{
    #pragma unroll
    for (int i = 0; i < 2; ++i) {
        int c = tid + i * 256;            // 0..511
        int row = c >> 2, col = c & 3;
        uint32_t phys = (uint32_t)(row * 64 + ((col ^ ((row >> 1) & 3)) << 4));
        size_t gA = (size_t)(m0 + row) * F + k0 + col * 8;
        int szA = (m0 + row < M) ? 16 : 0;
        cp_async16(s + phys,         Ah + gA, szA);
        cp_async16(s + 8192 + phys,  Al + gA, szA);
        size_t gB = (size_t)(n0 + row) * F + k0 + col * 8;
        cp_async16(s + 16384 + phys, Bh + gB, 16);
        cp_async16(s + 24576 + phys, Bl + gB, 16);
    }
    asm volatile("cp.async.commit_group;" ::: "memory");
}

__global__ __launch_bounds__(256) void gemm_mma(
    const __nv_bfloat16* __restrict__ Ah, const __nv_bfloat16* __restrict__ Al,
    const __nv_bfloat16* __restrict__ Bh, const __nv_bfloat16* __restrict__ Bl,
    const float* __restrict__ bias, float* __restrict__ C, int M, int relu)
{
    extern __shared__ char smem[];
    const uint32_t sb = smem_to_u32(smem);
    const int tid = threadIdx.x;
    const int wid = tid >> 5, lid = tid & 31;
    const int m0 = blockIdx.y * 128, n0 = blockIdx.x * 128;
    const int wm = (wid & 3) * 32;     // warp m offset within tile
    const int wn = (wid >> 2) * 64;    // warp n offset within tile

    float acc[2][8][4];
    #pragma unroll
    for (int a = 0; a < 2; ++a)
        #pragma unroll
        for (int b = 0; b < 8; ++b)
            #pragma unroll
            for (int c = 0; c < 4; ++c) acc[a][b][c] = 0.f;

    load_stage(sb, m0, n0, M, 0, tid, Ah, Al, Bh, Bl);
    load_stage(sb + STAGE_BYTES, m0, n0, M, 32, tid, Ah, Al, Bh, Bl);

    const int NCH = F / 32;   // 16
    for (int ch = 0; ch < NCH; ++ch) {
        asm volatile("cp.async.wait_group 1;" ::: "memory");
        __syncthreads();
        const uint32_t s = sb + (ch & 1) * STAGE_BYTES;

        #pragma unroll
        for (int kk = 0; kk < 2; ++kk) {
            const int kc = (kk << 1);                 // base chunk of this k16: 0 or 2
            // --- A fragments (hi & lo), 2 m16 tiles ---
            uint32_t ahf[2][4], alf[2][4];
            #pragma unroll
            for (int mt = 0; mt < 2; ++mt) {
                int row = wm + mt * 16 + (lid & 15);
                int chunk = kc + ((lid >> 4) & 1);
                uint32_t ad = s + row * 64 + ((chunk ^ ((row >> 1) & 3)) << 4);
                ldsm4(ahf[mt], ad);
                ldsm4(alf[mt], ad + 8192);
            }
            // --- B pairs + MMAs ---
            #pragma unroll
            for (int p = 0; p < 4; ++p) {
                int row = wn + p * 16 + (lid & 7) + (((lid >> 4) & 1) << 3);
                int chunk = kc + ((lid >> 3) & 1);
                uint32_t bd = s + 16384 + row * 64 + ((chunk ^ ((row >> 1) & 3)) << 4);
                uint32_t bhf[4], blf[4];
                ldsm4(bhf, bd);
                ldsm4(blf, bd + 8192);
                #pragma unroll
                for (int mt = 0; mt < 2; ++mt) {
                    mma_bf16(acc[mt][2 * p],     ahf[mt], bhf);
                    mma_bf16(acc[mt][2 * p],     ahf[mt], blf);
                    mma_bf16(acc[mt][2 * p],     alf[mt], bhf);
                    mma_bf16(acc[mt][2 * p + 1], ahf[mt], bhf + 2);
                    mma_bf16(acc[mt][2 * p + 1], ahf[mt], blf + 2);
                    mma_bf16(acc[mt][2 * p + 1], alf[mt], bhf + 2);
                }
            }
        }
        __syncthreads();
        if (ch + 2 < NCH)
            load_stage(sb + (ch & 1) * STAGE_BYTES, m0, n0, M, (ch + 2) * 32,
                       tid, Ah, Al, Bh, Bl);
        else
            asm volatile("cp.async.commit_group;" ::: "memory");
    }

    // ---- epilogue: bias (+relu), fp32 writes ----
    #pragma unroll
    for (int mt = 0; mt < 2; ++mt) {
        int rbase = m0 + wm + mt * 16 + (lid >> 2);
        #pragma unroll
        for (int half = 0; half < 2; ++half) {
            int m = rbase + half * 8;
            if (m < M) {
                #pragma unroll
                for (int nt = 0; nt < 8; ++nt) {
                    int n = n0 + wn + nt * 8 + (lid & 3) * 2;
                    float2 o;
                    o.x = acc[mt][nt][half * 2 + 0] + bias[n];
                    o.y = acc[mt][nt][half * 2 + 1] + bias[n + 1];
                    if (relu) { o.x = fmaxf(o.x, 0.f); o.y = fmaxf(o.y, 0.f); }
                    *reinterpret_cast<float2*>(C + (size_t)m * F + n) = o;
                }
            }
        }
    }
}

// ==================== launcher ====================
extern "C" void kernel_launch(void* const* d_in, const int* in_sizes, int n_in,
                              void* d_out, int out_size) {
    const float* x   = (const float*)d_in[0];
    const float* W1  = (const float*)d_in[1];
    const float* b1  = (const float*)d_in[2];
    const float* W2  = (const float*)d_in[3];
    const float* b2  = (const float*)d_in[4];
    const float* W3  = (const float*)d_in[5];
    const float* b3  = (const float*)d_in[6];
    const int*   src = (const int*)d_in[7];
    const int*   dst = (const int*)d_in[8];

    float* out = (float*)d_out;
    float* h4 = out;                        // no relu
    float* h3 = out + (size_t)NN * F;       // relu
    float* h2 = out + 2 * (size_t)NN * F;   // relu

    float* h1 = nullptr;
    __nv_bfloat16 *Ahi = nullptr, *Alo = nullptr;
    __nv_bfloat16 *W1h = nullptr, *W1l = nullptr, *W2h = nullptr, *W2l = nullptr,
                  *W3h = nullptr, *W3l = nullptr;
    cudaGetSymbolAddress((void**)&h1,  g_h1);
    cudaGetSymbolAddress((void**)&Ahi, g_Ahi);
    cudaGetSymbolAddress((void**)&Alo, g_Alo);
    cudaGetSymbolAddress((void**)&W1h, g_W1hi);
    cudaGetSymbolAddress((void**)&W1l, g_W1lo);
    cudaGetSymbolAddress((void**)&W2h, g_W2hi);
    cudaGetSymbolAddress((void**)&W2l, g_W2lo);
    cudaGetSymbolAddress((void**)&W3h, g_W3hi);
    cudaGetSymbolAddress((void**)&W3l, g_W3lo);

    cudaFuncSetAttribute(gemm_mma, cudaFuncAttributeMaxDynamicSharedMemorySize, GEMM_SMEM);

    const int TB = 256;
    zero_kernel<<<(NN + TB - 1) / TB, TB>>>();
    degree_kernel<<<(NE + TB - 1) / TB, TB>>>(src, dst);
    norm_kernel<<<(NN + TB - 1) / TB, TB>>>();
    scan_kernel<<<1, 1024>>>();
    scatter_kernel<<<(NE + TB - 1) / TB, TB>>>(src, dst);

    dim3 wgrid(16, 16);
    dim3 wblk(32, 32);
    wsplit_kernel<<<wgrid, wblk>>>(W1, W1h, W1l);
    wsplit_kernel<<<wgrid, wblk>>>(W2, W2h, W2l);
    wsplit_kernel<<<wgrid, wblk>>>(W3, W3h, W3l);

    dim3 ggrid(4, (NN + 127) / 128);   // (N/128, ceil(M/128))

    // layer 1: h1 = relu(agg(x) @ W1 + b1)
    agg_kernel<<<NN, 128>>>(x, Ahi, Alo);
    gemm_mma<<<ggrid, 256, GEMM_SMEM>>>(Ahi, Alo, W1h, W1l, b1, h1, NN, 1);

    // layer 2: h2 = relu(agg(h1) @ W2 + b2)
    agg_kernel<<<NN, 128>>>(h1, Ahi, Alo);
    gemm_mma<<<ggrid, 256, GEMM_SMEM>>>(Ahi, Alo, W2h, W2l, b2, h2, NN, 1);

    // shared aggregation of h2 feeds h3 and h4
    agg_kernel<<<NN, 128>>>(h2, Ahi, Alo);
    gemm_mma<<<ggrid, 256, GEMM_SMEM>>>(Ahi, Alo, W2h, W2l, b2, h3, NN, 1);
    gemm_mma<<<ggrid, 256, GEMM_SMEM>>>(Ahi, Alo, W3h, W3l, b3, h4, NN, 0);
}

// round 4
// speedup vs baseline: 2.9241x; 1.0245x over previous
#include <cuda_runtime.h>
#include <cuda_bf16.h>
#include <cstdint>

#define NN 10000
#define NE 160000
#define F 512
#define F4 128
#define MSPLIT 5120            // first-half rows (40 m-blocks)
#define MA_BLK 40
#define MB_BLK 39              // covers 4880 remaining (guarded)

// ==================== scratch (device globals) ====================
__device__ int   g_deg_out[NN];
__device__ int   g_deg_in[NN];
__device__ float g_norm_out[NN];
__device__ float g_norm_in[NN];
__device__ int   g_off[NN + 1];
__device__ int   g_cnt[NN];
__device__ int   g_csr_src[NE];
__device__ float g_csr_w[NE];
__device__ float g_h1[(size_t)NN * F];
__device__ __nv_bfloat16 g_Ahi[(size_t)NN * F];
__device__ __nv_bfloat16 g_Alo[(size_t)NN * F];
__device__ __nv_bfloat16 g_W1hi[F * F], g_W1lo[F * F];
__device__ __nv_bfloat16 g_W2hi[F * F], g_W2lo[F * F];
__device__ __nv_bfloat16 g_W3hi[F * F], g_W3lo[F * F];

// ==================== PTX helpers (base-target features only) ====================
__device__ __forceinline__ uint32_t smem_to_u32(const void* p) {
    uint32_t a;
    asm("{ .reg .u64 t; cvta.to.shared.u64 t, %1; cvt.u32.u64 %0, t; }" : "=r"(a) : "l"(p));
    return a;
}
__device__ __forceinline__ void cp_async16(uint32_t dst, const void* src, int sz) {
    asm volatile("cp.async.cg.shared.global [%0], [%1], 16, %2;"
        :: "r"(dst), "l"(src), "r"(sz) : "memory");
}
__device__ __forceinline__ void ldsm4(uint32_t* r, uint32_t addr) {
    asm volatile("ldmatrix.sync.aligned.m8n8.x4.shared.b16 {%0,%1,%2,%3}, [%4];"
        : "=r"(r[0]), "=r"(r[1]), "=r"(r[2]), "=r"(r[3]) : "r"(addr));
}
__device__ __forceinline__ void mma_bf16(float* d, const uint32_t* a, const uint32_t* b) {
    asm volatile(
        "mma.sync.aligned.m16n8k16.row.col.f32.bf16.bf16.f32 "
        "{%0,%1,%2,%3}, {%4,%5,%6,%7}, {%8,%9}, {%0,%1,%2,%3};"
        : "+f"(d[0]), "+f"(d[1]), "+f"(d[2]), "+f"(d[3])
        : "r"(a[0]), "r"(a[1]), "r"(a[2]), "r"(a[3]), "r"(b[0]), "r"(b[1]));
}

// ==================== setup kernels ====================
__global__ void zero_kernel() {
    int i = blockIdx.x * blockDim.x + threadIdx.x;
    if (i < NN) { g_deg_out[i] = 0; g_deg_in[i] = 0; g_cnt[i] = 0; }
}

__global__ void degree_kernel(const int* __restrict__ src, const int* __restrict__ dst) {
    int e = blockIdx.x * blockDim.x + threadIdx.x;
    if (e < NE) {
        atomicAdd(&g_deg_out[src[e]], 1);
        atomicAdd(&g_deg_in[dst[e]], 1);
    }
}

// exclusive scan of g_deg_in -> g_off, PLUS norm computation (fused)
__global__ void scan_norm_kernel() {
    __shared__ int wsum[32];
    int tid = threadIdx.x;
    int base = tid * 10;
    int loc[10];
    int s = 0;
    #pragma unroll
    for (int i = 0; i < 10; ++i) {
        loc[i] = s;
        int idx = base + i;
        int d = (idx < NN) ? g_deg_in[idx] : 0;
        s += d;
        if (idx < NN) {
            int a = g_deg_out[idx];
            g_norm_out[idx] = a > 0 ? rsqrtf((float)a) : 0.f;
            g_norm_in[idx]  = d > 0 ? rsqrtf((float)d) : 0.f;
        }
    }
    int x = s;
    #pragma unroll
    for (int d = 1; d < 32; d <<= 1) {
        int y = __shfl_up_sync(0xffffffffu, x, d);
        if ((tid & 31) >= d) x += y;
    }
    if ((tid & 31) == 31) wsum[tid >> 5] = x;
    __syncthreads();
    if (tid < 32) {
        int w = wsum[tid];
        #pragma unroll
        for (int d = 1; d < 32; d <<= 1) {
            int y = __shfl_up_sync(0xffffffffu, w, d);
            if (tid >= d) w += y;
        }
        wsum[tid] = w;
    }
    __syncthreads();
    int pref = x - s + ((tid >= 32) ? wsum[(tid >> 5) - 1] : 0);
    #pragma unroll
    for (int i = 0; i < 10; ++i) {
        int idx = base + i;
        if (idx < NN) g_off[idx] = pref + loc[i];
    }
    if (tid == 1023) g_off[NN] = pref + s;
}

__global__ void scatter_kernel(const int* __restrict__ src, const int* __restrict__ dst) {
    int e = blockIdx.x * blockDim.x + threadIdx.x;
    if (e < NE) {
        int d = dst[e];
        int pos = g_off[d] + atomicAdd(&g_cnt[d], 1);
        int s = src[e];
        g_csr_src[pos] = s;
        g_csr_w[pos]   = g_norm_out[s];
    }
}

// all three W [512,512] k-major -> transposed hi/lo bf16 Wt[n][k]; z picks W
__global__ void wsplit3_kernel(const float* __restrict__ W1, const float* __restrict__ W2,
                               const float* __restrict__ W3,
                               __nv_bfloat16* __restrict__ O1h, __nv_bfloat16* __restrict__ O1l,
                               __nv_bfloat16* __restrict__ O2h, __nv_bfloat16* __restrict__ O2l,
                               __nv_bfloat16* __restrict__ O3h, __nv_bfloat16* __restrict__ O3l) {
    const float* W = (blockIdx.z == 0) ? W1 : (blockIdx.z == 1) ? W2 : W3;
    __nv_bfloat16* Oh = (blockIdx.z == 0) ? O1h : (blockIdx.z == 1) ? O2h : O3h;
    __nv_bfloat16* Ol = (blockIdx.z == 0) ? O1l : (blockIdx.z == 1) ? O2l : O3l;
    __shared__ float t[32][33];
    int n = blockIdx.x * 32 + threadIdx.x;
    int k = blockIdx.y * 32 + threadIdx.y;
    t[threadIdx.y][threadIdx.x] = W[(size_t)k * F + n];
    __syncthreads();
    int on = blockIdx.x * 32 + threadIdx.y;
    int ok = blockIdx.y * 32 + threadIdx.x;
    float v = t[threadIdx.x][threadIdx.y];
    __nv_bfloat16 h = __float2bfloat16(v);
    Oh[(size_t)on * F + ok] = h;
    Ol[(size_t)on * F + ok] = __float2bfloat16(v - __bfloat162float(h));
}

// ==================== aggregation: one CTA per dst node, 4x unrolled ====================
__global__ __launch_bounds__(128) void agg_kernel(const float* __restrict__ x,
                                                  __nv_bfloat16* __restrict__ ohi,
                                                  __nv_bfloat16* __restrict__ olo,
                                                  int nodeBase) {
    int node = nodeBase + blockIdx.x;
    int tid  = threadIdx.x;
    int beg = g_off[node];
    int end = g_off[node + 1];
    const float4* x4 = reinterpret_cast<const float4*>(x);
    float4 acc = make_float4(0.f, 0.f, 0.f, 0.f);
    int i = beg;
    for (; i + 4 <= end; i += 4) {
        int   s0 = __ldg(&g_csr_src[i + 0]);
        int   s1 = __ldg(&g_csr_src[i + 1]);
        int   s2 = __ldg(&g_csr_src[i + 2]);
        int   s3 = __ldg(&g_csr_src[i + 3]);
        float w0 = __ldg(&g_csr_w[i + 0]);
        float w1 = __ldg(&g_csr_w[i + 1]);
        float w2 = __ldg(&g_csr_w[i + 2]);
        float w3 = __ldg(&g_csr_w[i + 3]);
        float4 v0 = x4[(size_t)s0 * F4 + tid];
        float4 v1 = x4[(size_t)s1 * F4 + tid];
        float4 v2 = x4[(size_t)s2 * F4 + tid];
        float4 v3 = x4[(size_t)s3 * F4 + tid];
        acc.x = fmaf(w0, v0.x, acc.x); acc.y = fmaf(w0, v0.y, acc.y);
        acc.z = fmaf(w0, v0.z, acc.z); acc.w = fmaf(w0, v0.w, acc.w);
        acc.x = fmaf(w1, v1.x, acc.x); acc.y = fmaf(w1, v1.y, acc.y);
        acc.z = fmaf(w1, v1.z, acc.z); acc.w = fmaf(w1, v1.w, acc.w);
        acc.x = fmaf(w2, v2.x, acc.x); acc.y = fmaf(w2, v2.y, acc.y);
        acc.z = fmaf(w2, v2.z, acc.z); acc.w = fmaf(w2, v2.w, acc.w);
        acc.x = fmaf(w3, v3.x, acc.x); acc.y = fmaf(w3, v3.y, acc.y);
        acc.z = fmaf(w3, v3.z, acc.z); acc.w = fmaf(w3, v3.w, acc.w);
    }
    for (; i < end; ++i) {
        int   s = __ldg(&g_csr_src[i]);
        float w = __ldg(&g_csr_w[i]);
        float4 v = x4[(size_t)s * F4 + tid];
        acc.x = fmaf(w, v.x, acc.x);
        acc.y = fmaf(w, v.y, acc.y);
        acc.z = fmaf(w, v.z, acc.z);
        acc.w = fmaf(w, v.w, acc.w);
    }
    float ni = g_norm_in[node];
    float r[4] = {acc.x * ni, acc.y * ni, acc.z * ni, acc.w * ni};
    unsigned short hb[4], lb[4];
    #pragma unroll
    for (int j = 0; j < 4; ++j) {
        __nv_bfloat16 h = __float2bfloat16(r[j]);
        float hf = __bfloat162float(h);
        __nv_bfloat16 l = __float2bfloat16(r[j] - hf);
        hb[j] = __bfloat16_as_ushort(h);
        lb[j] = __bfloat16_as_ushort(l);
    }
    uint2 uh = make_uint2((uint32_t)hb[0] | ((uint32_t)hb[1] << 16),
                          (uint32_t)hb[2] | ((uint32_t)hb[3] << 16));
    uint2 ul = make_uint2((uint32_t)lb[0] | ((uint32_t)lb[1] << 16),
                          (uint32_t)lb[2] | ((uint32_t)lb[3] << 16));
    reinterpret_cast<uint2*>(ohi + (size_t)node * F)[tid] = uh;
    reinterpret_cast<uint2*>(olo + (size_t)node * F)[tid] = ul;
}

// ==================== mma.sync GEMM: C = (Ah+Al)@(Bh+Bl)^T + bias ====================
#define STAGE_BYTES 32768
#define GEMM_SMEM (2 * STAGE_BYTES)

__device__ __forceinline__ void load_stage(
    uint32_t s, int m0, int n0, int M, int k0, int tid,
    const __nv_bfloat16* __restrict__ Ah, const __nv_bfloat16* __restrict__ Al,
    const __nv_bfloat16* __restrict__ Bh, const __nv_bfloat16* __restrict__ Bl)
{
    #pragma unroll
    for (int i = 0; i < 2; ++i) {
        int c = tid + i * 256;            // 0..511
        int row = c >> 2, col = c & 3;
        uint32_t phys = (uint32_t)(row * 64 + ((col ^ ((row >> 1) & 3)) << 4));
        size_t gA = (size_t)(m0 + row) * F + k0 + col * 8;
        int szA = (m0 + row < M) ? 16 : 0;
        cp_async16(s + phys,         Ah + gA, szA);
        cp_async16(s + 8192 + phys,  Al + gA, szA);
        size_t gB = (size_t)(n0 + row) * F + k0 + col * 8;
        cp_async16(s + 16384 + phys, Bh + gB, 16);
        cp_async16(s + 24576 + phys, Bl + gB, 16);
    }
    asm volatile("cp.async.commit_group;" ::: "memory");
}

__global__ __launch_bounds__(256) void gemm_mma(
    const __nv_bfloat16* __restrict__ Ah, const __nv_bfloat16* __restrict__ Al,
    const __nv_bfloat16* __restrict__ Bh, const __nv_bfloat16* __restrict__ Bl,
    const float* __restrict__ bias, float* __restrict__ C, int mBase, int M, int relu)
{
    extern __shared__ char smem[];
    const uint32_t sb = smem_to_u32(smem);
    const int tid = threadIdx.x;
    const int wid = tid >> 5, lid = tid & 31;
    const int m0 = mBase + blockIdx.y * 128, n0 = blockIdx.x * 128;
    const int wm = (wid & 3) * 32;
    const int wn = (wid >> 2) * 64;

    float acc[2][8][4];
    #pragma unroll
    for (int a = 0; a < 2; ++a)
        #pragma unroll
        for (int b = 0; b < 8; ++b)
            #pragma unroll
            for (int c = 0; c < 4; ++c) acc[a][b][c] = 0.f;

    load_stage(sb, m0, n0, M, 0, tid, Ah, Al, Bh, Bl);
    load_stage(sb + STAGE_BYTES, m0, n0, M, 32, tid, Ah, Al, Bh, Bl);

    const int NCH = F / 32;   // 16
    for (int ch = 0; ch < NCH; ++ch) {
        asm volatile("cp.async.wait_group 1;" ::: "memory");
        __syncthreads();
        const uint32_t s = sb + (ch & 1) * STAGE_BYTES;

        #pragma unroll
        for (int kk = 0; kk < 2; ++kk) {
            const int kc = (kk << 1);
            uint32_t ahf[2][4], alf[2][4];
            #pragma unroll
            for (int mt = 0; mt < 2; ++mt) {
                int row = wm + mt * 16 + (lid & 15);
                int chunk = kc + ((lid >> 4) & 1);
                uint32_t ad = s + row * 64 + ((chunk ^ ((row >> 1) & 3)) << 4);
                ldsm4(ahf[mt], ad);
                ldsm4(alf[mt], ad + 8192);
            }
            #pragma unroll
            for (int p = 0; p < 4; ++p) {
                int row = wn + p * 16 + (lid & 7) + (((lid >> 4) & 1) << 3);
                int chunk = kc + ((lid >> 3) & 1);
                uint32_t bd = s + 16384 + row * 64 + ((chunk ^ ((row >> 1) & 3)) << 4);
                uint32_t bhf[4], blf[4];
                ldsm4(bhf, bd);
                ldsm4(blf, bd + 8192);
                #pragma unroll
                for (int mt = 0; mt < 2; ++mt) {
                    mma_bf16(acc[mt][2 * p],     ahf[mt], bhf);
                    mma_bf16(acc[mt][2 * p],     ahf[mt], blf);
                    mma_bf16(acc[mt][2 * p],     alf[mt], bhf);
                    mma_bf16(acc[mt][2 * p + 1], ahf[mt], bhf + 2);
                    mma_bf16(acc[mt][2 * p + 1], ahf[mt], blf + 2);
                    mma_bf16(acc[mt][2 * p + 1], alf[mt], bhf + 2);
                }
            }
        }
        __syncthreads();
        if (ch + 2 < NCH)
            load_stage(sb + (ch & 1) * STAGE_BYTES, m0, n0, M, (ch + 2) * 32,
                       tid, Ah, Al, Bh, Bl);
        else
            asm volatile("cp.async.commit_group;" ::: "memory");
    }

    #pragma unroll
    for (int mt = 0; mt < 2; ++mt) {
        int rbase = m0 + wm + mt * 16 + (lid >> 2);
        #pragma unroll
        for (int half = 0; half < 2; ++half) {
            int m = rbase + half * 8;
            if (m < M) {
                #pragma unroll
                for (int nt = 0; nt < 8; ++nt) {
                    int n = n0 + wn + nt * 8 + (lid & 3) * 2;
                    float2 o;
                    o.x = acc[mt][nt][half * 2 + 0] + bias[n];
                    o.y = acc[mt][nt][half * 2 + 1] + bias[n + 1];
                    if (relu) { o.x = fmaxf(o.x, 0.f); o.y = fmaxf(o.y, 0.f); }
                    *reinterpret_cast<float2*>(C + (size_t)m * F + n) = o;
                }
            }
        }
    }
}

// ==================== launcher ====================
extern "C" void kernel_launch(void* const* d_in, const int* in_sizes, int n_in,
                              void* d_out, int out_size) {
    const float* x   = (const float*)d_in[0];
    const float* W1  = (const float*)d_in[1];
    const float* b1  = (const float*)d_in[2];
    const float* W2  = (const float*)d_in[3];
    const float* b2  = (const float*)d_in[4];
    const float* W3  = (const float*)d_in[5];
    const float* b3  = (const float*)d_in[6];
    const int*   src = (const int*)d_in[7];
    const int*   dst = (const int*)d_in[8];

    float* out = (float*)d_out;
    float* h4 = out;
    float* h3 = out + (size_t)NN * F;
    float* h2 = out + 2 * (size_t)NN * F;

    float* h1 = nullptr;
    __nv_bfloat16 *Ahi = nullptr, *Alo = nullptr;
    __nv_bfloat16 *W1h = nullptr, *W1l = nullptr, *W2h = nullptr, *W2l = nullptr,
                  *W3h = nullptr, *W3l = nullptr;
    cudaGetSymbolAddress((void**)&h1,  g_h1);
    cudaGetSymbolAddress((void**)&Ahi, g_Ahi);
    cudaGetSymbolAddress((void**)&Alo, g_Alo);
    cudaGetSymbolAddress((void**)&W1h, g_W1hi);
    cudaGetSymbolAddress((void**)&W1l, g_W1lo);
    cudaGetSymbolAddress((void**)&W2h, g_W2hi);
    cudaGetSymbolAddress((void**)&W2l, g_W2lo);
    cudaGetSymbolAddress((void**)&W3h, g_W3hi);
    cudaGetSymbolAddress((void**)&W3l, g_W3lo);

    cudaFuncSetAttribute(gemm_mma, cudaFuncAttributeMaxDynamicSharedMemorySize, GEMM_SMEM);

    // side stream + events (created per call; kernel_launch only runs a few times)
    cudaStream_t s1;
    cudaStreamCreateWithFlags(&s1, cudaStreamNonBlocking);
    cudaEvent_t evFork, evW, evA1, evA2, evA3, evG1, evG2, evG3;
    cudaEventCreateWithFlags(&evFork, cudaEventDisableTiming);
    cudaEventCreateWithFlags(&evW,  cudaEventDisableTiming);
    cudaEventCreateWithFlags(&evA1, cudaEventDisableTiming);
    cudaEventCreateWithFlags(&evA2, cudaEventDisableTiming);
    cudaEventCreateWithFlags(&evA3, cudaEventDisableTiming);
    cudaEventCreateWithFlags(&evG1, cudaEventDisableTiming);
    cudaEventCreateWithFlags(&evG2, cudaEventDisableTiming);
    cudaEventCreateWithFlags(&evG3, cudaEventDisableTiming);

    // fork side stream; weight split runs concurrently with graph build
    cudaEventRecord(evFork, 0);
    cudaStreamWaitEvent(s1, evFork, 0);
    wsplit3_kernel<<<dim3(16, 16, 3), dim3(32, 32), 0, s1>>>(
        W1, W2, W3, W1h, W1l, W2h, W2l, W3h, W3l);
    cudaEventRecord(evW, s1);

    const int TB = 256;
    zero_kernel<<<(NN + TB - 1) / TB, TB>>>();
    degree_kernel<<<(NE + TB - 1) / TB, TB>>>(src, dst);
    scan_norm_kernel<<<1, 1024>>>();
    scatter_kernel<<<(NE + TB - 1) / TB, TB>>>(src, dst);

    dim3 gridA(4, MA_BLK), gridB(4, MB_BLK);

    // ---- layer 1 ----
    agg_kernel<<<MSPLIT, 128>>>(x, Ahi, Alo, 0);
    cudaEventRecord(evA1, 0);
    cudaStreamWaitEvent(s1, evA1, 0);
    agg_kernel<<<NN - MSPLIT, 128, 0, s1>>>(x, Ahi, Alo, MSPLIT);
    cudaStreamWaitEvent(0, evW, 0);
    gemm_mma<<<gridA, 256, GEMM_SMEM>>>(Ahi, Alo, W1h, W1l, b1, h1, 0, NN, 1);
    gemm_mma<<<gridB, 256, GEMM_SMEM, s1>>>(Ahi, Alo, W1h, W1l, b1, h1, MSPLIT, NN, 1);
    cudaEventRecord(evG1, s1);
    cudaStreamWaitEvent(0, evG1, 0);

    // ---- layer 2 ----
    agg_kernel<<<MSPLIT, 128>>>(h1, Ahi, Alo, 0);
    cudaEventRecord(evA2, 0);
    cudaStreamWaitEvent(s1, evA2, 0);
    agg_kernel<<<NN - MSPLIT, 128, 0, s1>>>(h1, Ahi, Alo, MSPLIT);
    gemm_mma<<<gridA, 256, GEMM_SMEM>>>(Ahi, Alo, W2h, W2l, b2, h2, 0, NN, 1);
    gemm_mma<<<gridB, 256, GEMM_SMEM, s1>>>(Ahi, Alo, W2h, W2l, b2, h2, MSPLIT, NN, 1);
    cudaEventRecord(evG2, s1);
    cudaStreamWaitEvent(0, evG2, 0);

    // ---- layer 3: shared agg feeds h3 (W2,relu) and h4 (W3,no relu) ----
    agg_kernel<<<MSPLIT, 128>>>(h2, Ahi, Alo, 0);
    cudaEventRecord(evA3, 0);
    cudaStreamWaitEvent(s1, evA3, 0);
    agg_kernel<<<NN - MSPLIT, 128, 0, s1>>>(h2, Ahi, Alo, MSPLIT);
    gemm_mma<<<gridA, 256, GEMM_SMEM>>>(Ahi, Alo, W2h, W2l, b2, h3, 0, NN, 1);
    gemm_mma<<<gridA, 256, GEMM_SMEM>>>(Ahi, Alo, W3h, W3l, b3, h4, 0, NN, 0);
    gemm_mma<<<gridB, 256, GEMM_SMEM, s1>>>(Ahi, Alo, W2h, W2l, b2, h3, MSPLIT, NN, 1);
    gemm_mma<<<gridB, 256, GEMM_SMEM, s1>>>(Ahi, Alo, W3h, W3l, b3, h4, MSPLIT, NN, 0);
    cudaEventRecord(evG3, s1);
    cudaStreamWaitEvent(0, evG3, 0);
    // (stream/events intentionally not destroyed: kernel_launch runs only a
    //  handful of times and destroying a stream mid-capture is illegal)
}

// round 5
// speedup vs baseline: 3.6014x; 1.2316x over previous
#include <cuda_runtime.h>
#include <cuda_bf16.h>
#include <cstdint>

#define NN 10000
#define NE 160000
#define F 512
#define F4 128
#define MSPLIT 5120
#define MA_BLK 40
#define MB_BLK 39

// ==================== scratch (device globals) ====================
__device__ int   g_deg_out[NN];
__device__ int   g_deg_in[NN];
__device__ float g_norm_out[NN];
__device__ float g_norm_in[NN];
__device__ int   g_off[NN + 1];
__device__ int   g_cnt[NN];
__device__ int   g_csr_src[NE];
__device__ float g_csr_w[NE];
__device__ float g_h1[(size_t)NN * F];
__device__ __nv_bfloat16 g_Ahi[(size_t)NN * F];
__device__ __nv_bfloat16 g_Alo[(size_t)NN * F];
__device__ __nv_bfloat16 g_W1hi[F * F], g_W1lo[F * F];
__device__ __nv_bfloat16 g_W2hi[F * F], g_W2lo[F * F];
__device__ __nv_bfloat16 g_W3hi[F * F], g_W3lo[F * F];

// ==================== PTX helpers ====================
__device__ __forceinline__ uint32_t smem_to_u32(const void* p) {
    uint32_t a;
    asm("{ .reg .u64 t; cvta.to.shared.u64 t, %1; cvt.u32.u64 %0, t; }" : "=r"(a) : "l"(p));
    return a;
}
__device__ __forceinline__ void cp_async16(uint32_t dst, const void* src, int sz) {
    asm volatile("cp.async.cg.shared.global [%0], [%1], 16, %2;"
        :: "r"(dst), "l"(src), "r"(sz) : "memory");
}
__device__ __forceinline__ void ldsm4(uint32_t* r, uint32_t addr) {
    asm volatile("ldmatrix.sync.aligned.m8n8.x4.shared.b16 {%0,%1,%2,%3}, [%4];"
        : "=r"(r[0]), "=r"(r[1]), "=r"(r[2]), "=r"(r[3]) : "r"(addr));
}
__device__ __forceinline__ void mma_bf16(float* d, const uint32_t* a, const uint32_t* b) {
    asm volatile(
        "mma.sync.aligned.m16n8k16.row.col.f32.bf16.bf16.f32 "
        "{%0,%1,%2,%3}, {%4,%5,%6,%7}, {%8,%9}, {%0,%1,%2,%3};"
        : "+f"(d[0]), "+f"(d[1]), "+f"(d[2]), "+f"(d[3])
        : "r"(a[0]), "r"(a[1]), "r"(a[2]), "r"(a[3]), "r"(b[0]), "r"(b[1]));
}

// ==================== setup kernels ====================
__global__ void zero_kernel() {
    int i = blockIdx.x * blockDim.x + threadIdx.x;
    if (i < NN) { g_deg_out[i] = 0; g_deg_in[i] = 0; g_cnt[i] = 0; }
}

__global__ void degree_kernel(const int* __restrict__ src, const int* __restrict__ dst) {
    int e = blockIdx.x * blockDim.x + threadIdx.x;
    if (e < NE) {
        atomicAdd(&g_deg_out[src[e]], 1);
        atomicAdd(&g_deg_in[dst[e]], 1);
    }
}

__global__ void norm_kernel() {
    int i = blockIdx.x * blockDim.x + threadIdx.x;
    if (i < NN) {
        int a = g_deg_out[i];
        int b = g_deg_in[i];
        g_norm_out[i] = a > 0 ? rsqrtf((float)a) : 0.f;
        g_norm_in[i]  = b > 0 ? rsqrtf((float)b) : 0.f;
    }
}

// exclusive scan of g_deg_in -> g_off
__global__ void scan_kernel() {
    __shared__ int wsum[32];
    int tid = threadIdx.x;
    int base = tid * 10;
    int loc[10];
    int s = 0;
    #pragma unroll
    for (int i = 0; i < 10; ++i) {
        loc[i] = s;
        int idx = base + i;
        s += (idx < NN) ? g_deg_in[idx] : 0;
    }
    int x = s;
    #pragma unroll
    for (int d = 1; d < 32; d <<= 1) {
        int y = __shfl_up_sync(0xffffffffu, x, d);
        if ((tid & 31) >= d) x += y;
    }
    if ((tid & 31) == 31) wsum[tid >> 5] = x;
    __syncthreads();
    if (tid < 32) {
        int w = wsum[tid];
        #pragma unroll
        for (int d = 1; d < 32; d <<= 1) {
            int y = __shfl_up_sync(0xffffffffu, w, d);
            if (tid >= d) w += y;
        }
        wsum[tid] = w;
    }
    __syncthreads();
    int pref = x - s + ((tid >= 32) ? wsum[(tid >> 5) - 1] : 0);
    #pragma unroll
    for (int i = 0; i < 10; ++i) {
        int idx = base + i;
        if (idx < NN) g_off[idx] = pref + loc[i];
    }
    if (tid == 1023) g_off[NN] = pref + s;
}

__global__ void scatter_kernel(const int* __restrict__ src, const int* __restrict__ dst) {
    int e = blockIdx.x * blockDim.x + threadIdx.x;
    if (e < NE) {
        int d = dst[e];
        int pos = g_off[d] + atomicAdd(&g_cnt[d], 1);
        int s = src[e];
        g_csr_src[pos] = s;
        g_csr_w[pos]   = g_norm_out[s];
    }
}

// all three W k-major -> transposed hi/lo bf16 Wt[n][k]
__global__ void wsplit3_kernel(const float* __restrict__ W1, const float* __restrict__ W2,
                               const float* __restrict__ W3,
                               __nv_bfloat16* __restrict__ O1h, __nv_bfloat16* __restrict__ O1l,
                               __nv_bfloat16* __restrict__ O2h, __nv_bfloat16* __restrict__ O2l,
                               __nv_bfloat16* __restrict__ O3h, __nv_bfloat16* __restrict__ O3l) {
    const float* W = (blockIdx.z == 0) ? W1 : (blockIdx.z == 1) ? W2 : W3;
    __nv_bfloat16* Oh = (blockIdx.z == 0) ? O1h : (blockIdx.z == 1) ? O2h : O3h;
    __nv_bfloat16* Ol = (blockIdx.z == 0) ? O1l : (blockIdx.z == 1) ? O2l : O3l;
    __shared__ float t[32][33];
    int n = blockIdx.x * 32 + threadIdx.x;
    int k = blockIdx.y * 32 + threadIdx.y;
    t[threadIdx.y][threadIdx.x] = W[(size_t)k * F + n];
    __syncthreads();
    int on = blockIdx.x * 32 + threadIdx.y;
    int ok = blockIdx.y * 32 + threadIdx.x;
    float v = t[threadIdx.x][threadIdx.y];
    __nv_bfloat16 h = __float2bfloat16(v);
    Oh[(size_t)on * F + ok] = h;
    Ol[(size_t)on * F + ok] = __float2bfloat16(v - __bfloat162float(h));
}

// ==================== aggregation ====================
__global__ __launch_bounds__(128) void agg_kernel(const float* __restrict__ x,
                                                  __nv_bfloat16* __restrict__ ohi,
                                                  __nv_bfloat16* __restrict__ olo,
                                                  int nodeBase) {
    int node = nodeBase + blockIdx.x;
    int tid  = threadIdx.x;
    int beg = g_off[node];
    int end = g_off[node + 1];
    const float4* x4 = reinterpret_cast<const float4*>(x);
    float4 acc = make_float4(0.f, 0.f, 0.f, 0.f);
    int i = beg;
    for (; i + 4 <= end; i += 4) {
        int   s0 = __ldg(&g_csr_src[i + 0]);
        int   s1 = __ldg(&g_csr_src[i + 1]);
        int   s2 = __ldg(&g_csr_src[i + 2]);
        int   s3 = __ldg(&g_csr_src[i + 3]);
        float w0 = __ldg(&g_csr_w[i + 0]);
        float w1 = __ldg(&g_csr_w[i + 1]);
        float w2 = __ldg(&g_csr_w[i + 2]);
        float w3 = __ldg(&g_csr_w[i + 3]);
        float4 v0 = x4[(size_t)s0 * F4 + tid];
        float4 v1 = x4[(size_t)s1 * F4 + tid];
        float4 v2 = x4[(size_t)s2 * F4 + tid];
        float4 v3 = x4[(size_t)s3 * F4 + tid];
        acc.x = fmaf(w0, v0.x, acc.x); acc.y = fmaf(w0, v0.y, acc.y);
        acc.z = fmaf(w0, v0.z, acc.z); acc.w = fmaf(w0, v0.w, acc.w);
        acc.x = fmaf(w1, v1.x, acc.x); acc.y = fmaf(w1, v1.y, acc.y);
        acc.z = fmaf(w1, v1.z, acc.z); acc.w = fmaf(w1, v1.w, acc.w);
        acc.x = fmaf(w2, v2.x, acc.x); acc.y = fmaf(w2, v2.y, acc.y);
        acc.z = fmaf(w2, v2.z, acc.z); acc.w = fmaf(w2, v2.w, acc.w);
        acc.x = fmaf(w3, v3.x, acc.x); acc.y = fmaf(w3, v3.y, acc.y);
        acc.z = fmaf(w3, v3.z, acc.z); acc.w = fmaf(w3, v3.w, acc.w);
    }
    for (; i < end; ++i) {
        int   s = __ldg(&g_csr_src[i]);
        float w = __ldg(&g_csr_w[i]);
        float4 v = x4[(size_t)s * F4 + tid];
        acc.x = fmaf(w, v.x, acc.x);
        acc.y = fmaf(w, v.y, acc.y);
        acc.z = fmaf(w, v.z, acc.z);
        acc.w = fmaf(w, v.w, acc.w);
    }
    float ni = g_norm_in[node];
    float r[4] = {acc.x * ni, acc.y * ni, acc.z * ni, acc.w * ni};
    unsigned short hb[4], lb[4];
    #pragma unroll
    for (int j = 0; j < 4; ++j) {
        __nv_bfloat16 h = __float2bfloat16(r[j]);
        float hf = __bfloat162float(h);
        __nv_bfloat16 l = __float2bfloat16(r[j] - hf);
        hb[j] = __bfloat16_as_ushort(h);
        lb[j] = __bfloat16_as_ushort(l);
    }
    uint2 uh = make_uint2((uint32_t)hb[0] | ((uint32_t)hb[1] << 16),
                          (uint32_t)hb[2] | ((uint32_t)hb[3] << 16));
    uint2 ul = make_uint2((uint32_t)lb[0] | ((uint32_t)lb[1] << 16),
                          (uint32_t)lb[2] | ((uint32_t)lb[3] << 16));
    reinterpret_cast<uint2*>(ohi + (size_t)node * F)[tid] = uh;
    reinterpret_cast<uint2*>(olo + (size_t)node * F)[tid] = ul;
}

// ==================== mma.sync GEMM v2 ====================
// CTA tile 128x64, 256 thr (8 warps, warp tile 32x32), BK=64, 2 CTAs/SM.
// Stage (48KB): Ah[0,16K) Al[16K,32K) Bh[32K,40K) Bl[40K,48K)
// Rows are 128B (64 bf16); 16B chunk c at row r stored at c^(r&7).
#define STAGE_BYTES 49152
#define GEMM_SMEM (2 * STAGE_BYTES)

__device__ __forceinline__ void load_stage(
    uint32_t s, int m0, int n0, int M, int k0, int tid,
    const __nv_bfloat16* __restrict__ Ah, const __nv_bfloat16* __restrict__ Al,
    const __nv_bfloat16* __restrict__ Bh, const __nv_bfloat16* __restrict__ Bl)
{
    // A: 128 rows x 8 chunks (1024 vectors) hi then lo; B: 64 x 8 (512) hi then lo
    #pragma unroll
    for (int i = 0; i < 4; ++i) {           // A hi
        int v = tid + i * 256;
        int row = v >> 3, c = v & 7;
        uint32_t phys = (uint32_t)(row * 128 + ((c ^ (row & 7)) << 4));
        size_t g = (size_t)(m0 + row) * F + k0 + c * 8;
        int sz = (m0 + row < M) ? 16 : 0;
        cp_async16(s + phys, Ah + g, sz);
        cp_async16(s + 16384 + phys, Al + g, sz);
    }
    #pragma unroll
    for (int i = 0; i < 2; ++i) {           // B hi+lo
        int v = tid + i * 256;
        int row = v >> 3, c = v & 7;
        uint32_t phys = (uint32_t)(row * 128 + ((c ^ (row & 7)) << 4));
        size_t g = (size_t)(n0 + row) * F + k0 + c * 8;
        cp_async16(s + 32768 + phys, Bh + g, 16);
        cp_async16(s + 40960 + phys, Bl + g, 16);
    }
    asm volatile("cp.async.commit_group;" ::: "memory");
}

// dual=0: grid.x = 8 (N=512), single B/bias/C. dual=1: grid.x = 16, low 8 -> (B,bias,C,relu),
// high 8 -> (B2,bias2,C2,no relu)
__global__ __launch_bounds__(256, 2) void gemm_mma(
    const __nv_bfloat16* __restrict__ Ah, const __nv_bfloat16* __restrict__ Al,
    const __nv_bfloat16* __restrict__ Bh, const __nv_bfloat16* __restrict__ Bl,
    const float* __restrict__ bias, float* __restrict__ C,
    const __nv_bfloat16* __restrict__ Bh2, const __nv_bfloat16* __restrict__ Bl2,
    const float* __restrict__ bias2, float* __restrict__ C2,
    int mBase, int M, int relu, int dual)
{
    extern __shared__ char smem[];
    const uint32_t sb = smem_to_u32(smem);
    const int tid = threadIdx.x;
    const int wid = tid >> 5, lid = tid & 31;
    int nb = blockIdx.x;
    if (dual && nb >= 8) {
        nb -= 8;
        Bh = Bh2; Bl = Bl2; bias = bias2; C = C2; relu = 0;
    }
    const int m0 = mBase + blockIdx.y * 128, n0 = nb * 64;
    const int wm = (wid >> 1) * 32;
    const int wn = (wid & 1) * 32;

    float acc[2][4][4];
    #pragma unroll
    for (int a = 0; a < 2; ++a)
        #pragma unroll
        for (int b = 0; b < 4; ++b)
            #pragma unroll
            for (int c = 0; c < 4; ++c) acc[a][b][c] = 0.f;

    load_stage(sb, m0, n0, M, 0, tid, Ah, Al, Bh, Bl);
    load_stage(sb + STAGE_BYTES, m0, n0, M, 64, tid, Ah, Al, Bh, Bl);

    const int NCH = F / 64;   // 8
    for (int ch = 0; ch < NCH; ++ch) {
        asm volatile("cp.async.wait_group 1;" ::: "memory");
        __syncthreads();
        const uint32_t s = sb + (ch & 1) * STAGE_BYTES;

        #pragma unroll
        for (int kk = 0; kk < 4; ++kk) {
            uint32_t ahf[2][4], alf[2][4];
            #pragma unroll
            for (int mt = 0; mt < 2; ++mt) {
                int row = wm + mt * 16 + (lid & 15);
                int c = kk * 2 + ((lid >> 4) & 1);
                uint32_t ad = s + row * 128 + ((c ^ (row & 7)) << 4);
                ldsm4(ahf[mt], ad);
                ldsm4(alf[mt], ad + 16384);
            }
            #pragma unroll
            for (int p = 0; p < 2; ++p) {
                int row = wn + p * 16 + (lid & 7) + (((lid >> 4) & 1) << 3);
                int c = kk * 2 + ((lid >> 3) & 1);
                uint32_t bd = s + 32768 + row * 128 + ((c ^ (row & 7)) << 4);
                uint32_t bhf[4], blf[4];
                ldsm4(bhf, bd);
                ldsm4(blf, bd + 8192);
                #pragma unroll
                for (int mt = 0; mt < 2; ++mt) {
                    mma_bf16(acc[mt][2 * p],     ahf[mt], bhf);
                    mma_bf16(acc[mt][2 * p],     ahf[mt], blf);
                    mma_bf16(acc[mt][2 * p],     alf[mt], bhf);
                    mma_bf16(acc[mt][2 * p + 1], ahf[mt], bhf + 2);
                    mma_bf16(acc[mt][2 * p + 1], ahf[mt], blf + 2);
                    mma_bf16(acc[mt][2 * p + 1], alf[mt], bhf + 2);
                }
            }
        }
        __syncthreads();
        if (ch + 2 < NCH)
            load_stage(sb + (ch & 1) * STAGE_BYTES, m0, n0, M, (ch + 2) * 64,
                       tid, Ah, Al, Bh, Bl);
        else
            asm volatile("cp.async.commit_group;" ::: "memory");
    }

    #pragma unroll
    for (int mt = 0; mt < 2; ++mt) {
        int rbase = m0 + wm + mt * 16 + (lid >> 2);
        #pragma unroll
        for (int half = 0; half < 2; ++half) {
            int m = rbase + half * 8;
            if (m < M) {
                #pragma unroll
                for (int nt = 0; nt < 4; ++nt) {
                    int n = n0 + wn + nt * 8 + (lid & 3) * 2;
                    float2 o;
                    o.x = acc[mt][nt][half * 2 + 0] + bias[n];
                    o.y = acc[mt][nt][half * 2 + 1] + bias[n + 1];
                    if (relu) { o.x = fmaxf(o.x, 0.f); o.y = fmaxf(o.y, 0.f); }
                    *reinterpret_cast<float2*>(C + (size_t)m * F + n) = o;
                }
            }
        }
    }
}

// ==================== launcher ====================
extern "C" void kernel_launch(void* const* d_in, const int* in_sizes, int n_in,
                              void* d_out, int out_size) {
    const float* x   = (const float*)d_in[0];
    const float* W1  = (const float*)d_in[1];
    const float* b1  = (const float*)d_in[2];
    const float* W2  = (const float*)d_in[3];
    const float* b2  = (const float*)d_in[4];
    const float* W3  = (const float*)d_in[5];
    const float* b3  = (const float*)d_in[6];
    const int*   src = (const int*)d_in[7];
    const int*   dst = (const int*)d_in[8];

    float* out = (float*)d_out;
    float* h4 = out;
    float* h3 = out + (size_t)NN * F;
    float* h2 = out + 2 * (size_t)NN * F;

    float* h1 = nullptr;
    __nv_bfloat16 *Ahi = nullptr, *Alo = nullptr;
    __nv_bfloat16 *W1h = nullptr, *W1l = nullptr, *W2h = nullptr, *W2l = nullptr,
                  *W3h = nullptr, *W3l = nullptr;
    cudaGetSymbolAddress((void**)&h1,  g_h1);
    cudaGetSymbolAddress((void**)&Ahi, g_Ahi);
    cudaGetSymbolAddress((void**)&Alo, g_Alo);
    cudaGetSymbolAddress((void**)&W1h, g_W1hi);
    cudaGetSymbolAddress((void**)&W1l, g_W1lo);
    cudaGetSymbolAddress((void**)&W2h, g_W2hi);
    cudaGetSymbolAddress((void**)&W2l, g_W2lo);
    cudaGetSymbolAddress((void**)&W3h, g_W3hi);
    cudaGetSymbolAddress((void**)&W3l, g_W3lo);

    cudaFuncSetAttribute(gemm_mma, cudaFuncAttributeMaxDynamicSharedMemorySize, GEMM_SMEM);

    cudaStream_t s1;
    cudaStreamCreateWithFlags(&s1, cudaStreamNonBlocking);
    cudaEvent_t evFork, evW, evA1, evA2, evA3, evG1, evG2, evG3;
    cudaEventCreateWithFlags(&evFork, cudaEventDisableTiming);
    cudaEventCreateWithFlags(&evW,  cudaEventDisableTiming);
    cudaEventCreateWithFlags(&evA1, cudaEventDisableTiming);
    cudaEventCreateWithFlags(&evA2, cudaEventDisableTiming);
    cudaEventCreateWithFlags(&evA3, cudaEventDisableTiming);
    cudaEventCreateWithFlags(&evG1, cudaEventDisableTiming);
    cudaEventCreateWithFlags(&evG2, cudaEventDisableTiming);
    cudaEventCreateWithFlags(&evG3, cudaEventDisableTiming);

    // fork side stream: weight split + norms run off the critical path
    cudaEventRecord(evFork, 0);
    cudaStreamWaitEvent(s1, evFork, 0);
    wsplit3_kernel<<<dim3(16, 16, 3), dim3(32, 32), 0, s1>>>(
        W1, W2, W3, W1h, W1l, W2h, W2l, W3h, W3l);
    cudaEventRecord(evW, s1);

    const int TB = 256;
    zero_kernel<<<(NN + TB - 1) / TB, TB>>>();
    degree_kernel<<<(NE + TB - 1) / TB, TB>>>(src, dst);
    norm_kernel<<<(NN + TB - 1) / TB, TB>>>();
    scan_kernel<<<1, 1024>>>();
    scatter_kernel<<<(NE + TB - 1) / TB, TB>>>(src, dst);

    dim3 gridA(8, MA_BLK), gridB(8, MB_BLK);
    dim3 gridA2(16, MA_BLK), gridB2(16, MB_BLK);

    // ---- layer 1 ----
    agg_kernel<<<MSPLIT, 128>>>(x, Ahi, Alo, 0);
    cudaEventRecord(evA1, 0);
    cudaStreamWaitEvent(s1, evA1, 0);
    agg_kernel<<<NN - MSPLIT, 128, 0, s1>>>(x, Ahi, Alo, MSPLIT);
    cudaStreamWaitEvent(0, evW, 0);
    gemm_mma<<<gridA, 256, GEMM_SMEM>>>(Ahi, Alo, W1h, W1l, b1, h1,
                                        nullptr, nullptr, nullptr, nullptr, 0, NN, 1, 0);
    gemm_mma<<<gridB, 256, GEMM_SMEM, s1>>>(Ahi, Alo, W1h, W1l, b1, h1,
                                            nullptr, nullptr, nullptr, nullptr, MSPLIT, NN, 1, 0);
    cudaEventRecord(evG1, s1);
    cudaStreamWaitEvent(0, evG1, 0);

    // ---- layer 2 ----
    agg_kernel<<<MSPLIT, 128>>>(h1, Ahi, Alo, 0);
    cudaEventRecord(evA2, 0);
    cudaStreamWaitEvent(s1, evA2, 0);
    agg_kernel<<<NN - MSPLIT, 128, 0, s1>>>(h1, Ahi, Alo, MSPLIT);
    gemm_mma<<<gridA, 256, GEMM_SMEM>>>(Ahi, Alo, W2h, W2l, b2, h2,
                                        nullptr, nullptr, nullptr, nullptr, 0, NN, 1, 0);
    gemm_mma<<<gridB, 256, GEMM_SMEM, s1>>>(Ahi, Alo, W2h, W2l, b2, h2,
                                            nullptr, nullptr, nullptr, nullptr, MSPLIT, NN, 1, 0);
    cudaEventRecord(evG2, s1);
    cudaStreamWaitEvent(0, evG2, 0);

    // ---- layer 3: shared agg feeds h3 (W2,relu) and h4 (W3) in one dual GEMM ----
    agg_kernel<<<MSPLIT, 128>>>(h2, Ahi, Alo, 0);
    cudaEventRecord(evA3, 0);
    cudaStreamWaitEvent(s1, evA3, 0);
    agg_kernel<<<NN - MSPLIT, 128, 0, s1>>>(h2, Ahi, Alo, MSPLIT);
    gemm_mma<<<gridA2, 256, GEMM_SMEM>>>(Ahi, Alo, W2h, W2l, b2, h3,
                                         W3h, W3l, b3, h4, 0, NN, 1, 1);
    gemm_mma<<<gridB2, 256, GEMM_SMEM, s1>>>(Ahi, Alo, W2h, W2l, b2, h3,
                                             W3h, W3l, b3, h4, MSPLIT, NN, 1, 1);
    cudaEventRecord(evG3, s1);
    cudaStreamWaitEvent(0, evG3, 0);
}

// round 6
// speedup vs baseline: 4.2593x; 1.1827x over previous
#include <cuda_runtime.h>
#include <cuda_fp16.h>
#include <cstdint>

#define NN 10000
#define NE 160000
#define F 512
#define F4 128
#define MSPLIT 5120
#define MA_BLK 40
#define MB_BLK 39

// ==================== scratch (device globals) ====================
__device__ int   g_ivec[3][NN];     // [0]=deg_out [1]=deg_in [2]=cnt  (one memset)
#define g_deg_out (g_ivec[0])
#define g_deg_in  (g_ivec[1])
#define g_cnt     (g_ivec[2])
__device__ int   g_off[NN + 1];
__device__ int   g_csr_src[NE];
__device__ float g_csr_w[NE];
__device__ float g_h1[(size_t)NN * F];
__device__ __half g_Ahi[(size_t)NN * F];
__device__ __half g_Alo[(size_t)NN * F];
__device__ __half g_W1h[F * F], g_W2h[F * F], g_W3h[F * F];

// ==================== PTX helpers ====================
__device__ __forceinline__ uint32_t smem_to_u32(const void* p) {
    uint32_t a;
    asm("{ .reg .u64 t; cvta.to.shared.u64 t, %1; cvt.u32.u64 %0, t; }" : "=r"(a) : "l"(p));
    return a;
}
__device__ __forceinline__ void cp_async16(uint32_t dst, const void* src, int sz) {
    asm volatile("cp.async.cg.shared.global [%0], [%1], 16, %2;"
        :: "r"(dst), "l"(src), "r"(sz) : "memory");
}
__device__ __forceinline__ void ldsm4(uint32_t* r, uint32_t addr) {
    asm volatile("ldmatrix.sync.aligned.m8n8.x4.shared.b16 {%0,%1,%2,%3}, [%4];"
        : "=r"(r[0]), "=r"(r[1]), "=r"(r[2]), "=r"(r[3]) : "r"(addr));
}
__device__ __forceinline__ void mma_f16(float* d, const uint32_t* a, const uint32_t* b) {
    asm volatile(
        "mma.sync.aligned.m16n8k16.row.col.f32.f16.f16.f32 "
        "{%0,%1,%2,%3}, {%4,%5,%6,%7}, {%8,%9}, {%0,%1,%2,%3};"
        : "+f"(d[0]), "+f"(d[1]), "+f"(d[2]), "+f"(d[3])
        : "r"(a[0]), "r"(a[1]), "r"(a[2]), "r"(a[3]), "r"(b[0]), "r"(b[1]));
}

// ==================== setup kernels ====================
__global__ void degree_kernel(const int* __restrict__ src, const int* __restrict__ dst) {
    int e = blockIdx.x * blockDim.x + threadIdx.x;
    if (e < NE) {
        atomicAdd(&g_deg_out[src[e]], 1);
        atomicAdd(&g_deg_in[dst[e]], 1);
    }
}

// exclusive scan of g_deg_in -> g_off; 1024 threads x 12 elems (int4 x3)
__global__ void scan_kernel() {
    __shared__ int wsum[32];
    int tid = threadIdx.x;
    const int4* din4 = reinterpret_cast<const int4*>(g_deg_in);  // spills into zeroed cnt
    int v[12];
    #pragma unroll
    for (int j = 0; j < 3; ++j) {
        int4 q = din4[tid * 3 + j];
        v[j * 4 + 0] = q.x; v[j * 4 + 1] = q.y; v[j * 4 + 2] = q.z; v[j * 4 + 3] = q.w;
    }
    int loc[12];
    int s = 0;
    #pragma unroll
    for (int i = 0; i < 12; ++i) { loc[i] = s; s += v[i]; }
    int x = s;
    #pragma unroll
    for (int d = 1; d < 32; d <<= 1) {
        int y = __shfl_up_sync(0xffffffffu, x, d);
        if ((tid & 31) >= d) x += y;
    }
    if ((tid & 31) == 31) wsum[tid >> 5] = x;
    __syncthreads();
    if (tid < 32) {
        int w = wsum[tid];
        #pragma unroll
        for (int d = 1; d < 32; d <<= 1) {
            int y = __shfl_up_sync(0xffffffffu, w, d);
            if (tid >= d) w += y;
        }
        wsum[tid] = w;
    }
    __syncthreads();
    int pref = x - s + ((tid >= 32) ? wsum[(tid >> 5) - 1] : 0);
    int base = tid * 12;
    #pragma unroll
    for (int i = 0; i < 12; ++i) {
        int idx = base + i;
        if (idx < NN) g_off[idx] = pref + loc[i];
    }
    if (tid == 1023) g_off[NN] = pref + s;
}

__global__ void scatter_kernel(const int* __restrict__ src, const int* __restrict__ dst) {
    int e = blockIdx.x * blockDim.x + threadIdx.x;
    if (e < NE) {
        int d = dst[e];
        int pos = g_off[d] + atomicAdd(&g_cnt[d], 1);
        int s = src[e];
        g_csr_src[pos] = s;
        g_csr_w[pos]   = rsqrtf((float)g_deg_out[s]);   // s is an edge src -> deg>=1
    }
}

// all three W k-major -> transposed single-fp16 Wt[n][k]
__global__ void wsplit3_kernel(const float* __restrict__ W1, const float* __restrict__ W2,
                               const float* __restrict__ W3,
                               __half* __restrict__ O1, __half* __restrict__ O2,
                               __half* __restrict__ O3) {
    const float* W = (blockIdx.z == 0) ? W1 : (blockIdx.z == 1) ? W2 : W3;
    __half* Oh = (blockIdx.z == 0) ? O1 : (blockIdx.z == 1) ? O2 : O3;
    __shared__ float t[32][33];
    int n = blockIdx.x * 32 + threadIdx.x;
    int k = blockIdx.y * 32 + threadIdx.y;
    t[threadIdx.y][threadIdx.x] = W[(size_t)k * F + n];
    __syncthreads();
    int on = blockIdx.x * 32 + threadIdx.y;
    int ok = blockIdx.y * 32 + threadIdx.x;
    Oh[(size_t)on * F + ok] = __float2half_rn(t[threadIdx.x][threadIdx.y]);
}

// ==================== aggregation ====================
__global__ __launch_bounds__(128) void agg_kernel(const float* __restrict__ x,
                                                  __half* __restrict__ ohi,
                                                  __half* __restrict__ olo,
                                                  int nodeBase) {
    int node = nodeBase + blockIdx.x;
    int tid  = threadIdx.x;
    int beg = g_off[node];
    int end = g_off[node + 1];
    const float4* x4 = reinterpret_cast<const float4*>(x);
    float4 acc = make_float4(0.f, 0.f, 0.f, 0.f);
    int i = beg;
    for (; i + 4 <= end; i += 4) {
        int   s0 = __ldg(&g_csr_src[i + 0]);
        int   s1 = __ldg(&g_csr_src[i + 1]);
        int   s2 = __ldg(&g_csr_src[i + 2]);
        int   s3 = __ldg(&g_csr_src[i + 3]);
        float w0 = __ldg(&g_csr_w[i + 0]);
        float w1 = __ldg(&g_csr_w[i + 1]);
        float w2 = __ldg(&g_csr_w[i + 2]);
        float w3 = __ldg(&g_csr_w[i + 3]);
        float4 v0 = x4[(size_t)s0 * F4 + tid];
        float4 v1 = x4[(size_t)s1 * F4 + tid];
        float4 v2 = x4[(size_t)s2 * F4 + tid];
        float4 v3 = x4[(size_t)s3 * F4 + tid];
        acc.x = fmaf(w0, v0.x, acc.x); acc.y = fmaf(w0, v0.y, acc.y);
        acc.z = fmaf(w0, v0.z, acc.z); acc.w = fmaf(w0, v0.w, acc.w);
        acc.x = fmaf(w1, v1.x, acc.x); acc.y = fmaf(w1, v1.y, acc.y);
        acc.z = fmaf(w1, v1.z, acc.z); acc.w = fmaf(w1, v1.w, acc.w);
        acc.x = fmaf(w2, v2.x, acc.x); acc.y = fmaf(w2, v2.y, acc.y);
        acc.z = fmaf(w2, v2.z, acc.z); acc.w = fmaf(w2, v2.w, acc.w);
        acc.x = fmaf(w3, v3.x, acc.x); acc.y = fmaf(w3, v3.y, acc.y);
        acc.z = fmaf(w3, v3.z, acc.z); acc.w = fmaf(w3, v3.w, acc.w);
    }
    for (; i < end; ++i) {
        int   s = __ldg(&g_csr_src[i]);
        float w = __ldg(&g_csr_w[i]);
        float4 v = x4[(size_t)s * F4 + tid];
        acc.x = fmaf(w, v.x, acc.x);
        acc.y = fmaf(w, v.y, acc.y);
        acc.z = fmaf(w, v.z, acc.z);
        acc.w = fmaf(w, v.w, acc.w);
    }
    float ni = (end > beg) ? rsqrtf((float)(end - beg)) : 0.f;
    float r[4] = {acc.x * ni, acc.y * ni, acc.z * ni, acc.w * ni};
    unsigned short hb[4], lb[4];
    #pragma unroll
    for (int j = 0; j < 4; ++j) {
        __half h = __float2half_rn(r[j]);
        float hf = __half2float(h);
        __half l = __float2half_rn(r[j] - hf);
        hb[j] = __half_as_ushort(h);
        lb[j] = __half_as_ushort(l);
    }
    uint2 uh = make_uint2((uint32_t)hb[0] | ((uint32_t)hb[1] << 16),
                          (uint32_t)hb[2] | ((uint32_t)hb[3] << 16));
    uint2 ul = make_uint2((uint32_t)lb[0] | ((uint32_t)lb[1] << 16),
                          (uint32_t)lb[2] | ((uint32_t)lb[3] << 16));
    reinterpret_cast<uint2*>(ohi + (size_t)node * F)[tid] = uh;
    reinterpret_cast<uint2*>(olo + (size_t)node * F)[tid] = ul;
}

// ==================== mma.sync GEMM: C = (Ah+Al)@B^T + bias ====================
// A: fp16 hi/lo [M,512] row-major (2-term split, error 2^-22).
// B: single fp16 [512,512] n-major (error 2^-11 -> ~3e-4 norm rel err).
// CTA 128x64, 256 thr, BK=64, 2 stages. Stage (40KB): Ah[0,16K) Al[16K,32K) B[32K,40K)
#define STAGE_BYTES 40960
#define GEMM_SMEM (2 * STAGE_BYTES)

__device__ __forceinline__ void load_stage(
    uint32_t s, int m0, int n0, int M, int k0, int tid,
    const __half* __restrict__ Ah, const __half* __restrict__ Al,
    const __half* __restrict__ B)
{
    #pragma unroll
    for (int i = 0; i < 4; ++i) {           // A hi + lo (1024 vectors each)
        int v = tid + i * 256;
        int row = v >> 3, c = v & 7;
        uint32_t phys = (uint32_t)(row * 128 + ((c ^ (row & 7)) << 4));
        size_t g = (size_t)(m0 + row) * F + k0 + c * 8;
        int sz = (m0 + row < M) ? 16 : 0;
        cp_async16(s + phys, Ah + g, sz);
        cp_async16(s + 16384 + phys, Al + g, sz);
    }
    #pragma unroll
    for (int i = 0; i < 2; ++i) {           // B (512 vectors)
        int v = tid + i * 256;
        int row = v >> 3, c = v & 7;
        uint32_t phys = (uint32_t)(row * 128 + ((c ^ (row & 7)) << 4));
        size_t g = (size_t)(n0 + row) * F + k0 + c * 8;
        cp_async16(s + 32768 + phys, B + g, 16);
    }
    asm volatile("cp.async.commit_group;" ::: "memory");
}

// dual=0: grid.x=8 single output; dual=1: grid.x=16, high 8 -> (B2,bias2,C2,no relu)
__global__ __launch_bounds__(256, 2) void gemm_mma(
    const __half* __restrict__ Ah, const __half* __restrict__ Al,
    const __half* __restrict__ B, const float* __restrict__ bias, float* __restrict__ C,
    const __half* __restrict__ B2, const float* __restrict__ bias2, float* __restrict__ C2,
    int mBase, int M, int relu, int dual)
{
    extern __shared__ char smem[];
    const uint32_t sb = smem_to_u32(smem);
    const int tid = threadIdx.x;
    const int wid = tid >> 5, lid = tid & 31;
    int nb = blockIdx.x;
    if (dual && nb >= 8) {
        nb -= 8;
        B = B2; bias = bias2; C = C2; relu = 0;
    }
    const int m0 = mBase + blockIdx.y * 128, n0 = nb * 64;
    const int wm = (wid >> 1) * 32;
    const int wn = (wid & 1) * 32;

    float acc[2][4][4];
    #pragma unroll
    for (int a = 0; a < 2; ++a)
        #pragma unroll
        for (int b = 0; b < 4; ++b)
            #pragma unroll
            for (int c = 0; c < 4; ++c) acc[a][b][c] = 0.f;

    load_stage(sb, m0, n0, M, 0, tid, Ah, Al, B);
    load_stage(sb + STAGE_BYTES, m0, n0, M, 64, tid, Ah, Al, B);

    const int NCH = F / 64;   // 8
    for (int ch = 0; ch < NCH; ++ch) {
        asm volatile("cp.async.wait_group 1;" ::: "memory");
        __syncthreads();
        const uint32_t s = sb + (ch & 1) * STAGE_BYTES;

        #pragma unroll
        for (int kk = 0; kk < 4; ++kk) {
            uint32_t ahf[2][4], alf[2][4];
            #pragma unroll
            for (int mt = 0; mt < 2; ++mt) {
                int row = wm + mt * 16 + (lid & 15);
                int c = kk * 2 + ((lid >> 4) & 1);
                uint32_t ad = s + row * 128 + ((c ^ (row & 7)) << 4);
                ldsm4(ahf[mt], ad);
                ldsm4(alf[mt], ad + 16384);
            }
            #pragma unroll
            for (int p = 0; p < 2; ++p) {
                int row = wn + p * 16 + (lid & 7) + (((lid >> 4) & 1) << 3);
                int c = kk * 2 + ((lid >> 3) & 1);
                uint32_t bd = s + 32768 + row * 128 + ((c ^ (row & 7)) << 4);
                uint32_t bf[4];
                ldsm4(bf, bd);
                #pragma unroll
                for (int mt = 0; mt < 2; ++mt) {
                    mma_f16(acc[mt][2 * p],     ahf[mt], bf);
                    mma_f16(acc[mt][2 * p],     alf[mt], bf);
                    mma_f16(acc[mt][2 * p + 1], ahf[mt], bf + 2);
                    mma_f16(acc[mt][2 * p + 1], alf[mt], bf + 2);
                }
            }
        }
        __syncthreads();
        if (ch + 2 < NCH)
            load_stage(sb + (ch & 1) * STAGE_BYTES, m0, n0, M, (ch + 2) * 64, tid, Ah, Al, B);
        else
            asm volatile("cp.async.commit_group;" ::: "memory");
    }

    #pragma unroll
    for (int mt = 0; mt < 2; ++mt) {
        int rbase = m0 + wm + mt * 16 + (lid >> 2);
        #pragma unroll
        for (int half = 0; half < 2; ++half) {
            int m = rbase + half * 8;
            if (m < M) {
                #pragma unroll
                for (int nt = 0; nt < 4; ++nt) {
                    int n = n0 + wn + nt * 8 + (lid & 3) * 2;
                    float2 o;
                    o.x = acc[mt][nt][half * 2 + 0] + bias[n];
                    o.y = acc[mt][nt][half * 2 + 1] + bias[n + 1];
                    if (relu) { o.x = fmaxf(o.x, 0.f); o.y = fmaxf(o.y, 0.f); }
                    *reinterpret_cast<float2*>(C + (size_t)m * F + n) = o;
                }
            }
        }
    }
}

// ==================== launcher ====================
extern "C" void kernel_launch(void* const* d_in, const int* in_sizes, int n_in,
                              void* d_out, int out_size) {
    const float* x   = (const float*)d_in[0];
    const float* W1  = (const float*)d_in[1];
    const float* b1  = (const float*)d_in[2];
    const float* W2  = (const float*)d_in[3];
    const float* b2  = (const float*)d_in[4];
    const float* W3  = (const float*)d_in[5];
    const float* b3  = (const float*)d_in[6];
    const int*   src = (const int*)d_in[7];
    const int*   dst = (const int*)d_in[8];

    float* out = (float*)d_out;
    float* h4 = out;
    float* h3 = out + (size_t)NN * F;
    float* h2 = out + 2 * (size_t)NN * F;

    float* h1 = nullptr;
    void* ivec = nullptr;
    __half *Ahi = nullptr, *Alo = nullptr, *W1h = nullptr, *W2h = nullptr, *W3h = nullptr;
    cudaGetSymbolAddress(&ivec, g_ivec);
    cudaGetSymbolAddress((void**)&h1,  g_h1);
    cudaGetSymbolAddress((void**)&Ahi, g_Ahi);
    cudaGetSymbolAddress((void**)&Alo, g_Alo);
    cudaGetSymbolAddress((void**)&W1h, g_W1h);
    cudaGetSymbolAddress((void**)&W2h, g_W2h);
    cudaGetSymbolAddress((void**)&W3h, g_W3h);

    cudaFuncSetAttribute(gemm_mma, cudaFuncAttributeMaxDynamicSharedMemorySize, GEMM_SMEM);

    cudaStream_t s1;
    cudaStreamCreateWithFlags(&s1, cudaStreamNonBlocking);
    cudaEvent_t evFork, evW, evA1, evA2, evA3, evG1, evG2, evG3;
    cudaEventCreateWithFlags(&evFork, cudaEventDisableTiming);
    cudaEventCreateWithFlags(&evW,  cudaEventDisableTiming);
    cudaEventCreateWithFlags(&evA1, cudaEventDisableTiming);
    cudaEventCreateWithFlags(&evA2, cudaEventDisableTiming);
    cudaEventCreateWithFlags(&evA3, cudaEventDisableTiming);
    cudaEventCreateWithFlags(&evG1, cudaEventDisableTiming);
    cudaEventCreateWithFlags(&evG2, cudaEventDisableTiming);
    cudaEventCreateWithFlags(&evG3, cudaEventDisableTiming);

    // fork side stream: weight transpose+quantize off critical path
    cudaEventRecord(evFork, 0);
    cudaStreamWaitEvent(s1, evFork, 0);
    wsplit3_kernel<<<dim3(16, 16, 3), dim3(32, 32), 0, s1>>>(W1, W2, W3, W1h, W2h, W3h);
    cudaEventRecord(evW, s1);

    const int TB = 256;
    cudaMemsetAsync(ivec, 0, sizeof(int) * 3 * NN, 0);
    degree_kernel<<<(NE + TB - 1) / TB, TB>>>(src, dst);
    scan_kernel<<<1, 1024>>>();
    scatter_kernel<<<(NE + TB - 1) / TB, TB>>>(src, dst);

    dim3 gridA(8, MA_BLK), gridB(8, MB_BLK);
    dim3 gridA2(16, MA_BLK), gridB2(16, MB_BLK);

    // ---- layer 1 ----
    agg_kernel<<<MSPLIT, 128>>>(x, Ahi, Alo, 0);
    cudaEventRecord(evA1, 0);
    cudaStreamWaitEvent(s1, evA1, 0);
    agg_kernel<<<NN - MSPLIT, 128, 0, s1>>>(x, Ahi, Alo, MSPLIT);
    cudaStreamWaitEvent(0, evW, 0);
    gemm_mma<<<gridA, 256, GEMM_SMEM>>>(Ahi, Alo, W1h, b1, h1,
                                        nullptr, nullptr, nullptr, 0, NN, 1, 0);
    gemm_mma<<<gridB, 256, GEMM_SMEM, s1>>>(Ahi, Alo, W1h, b1, h1,
                                            nullptr, nullptr, nullptr, MSPLIT, NN, 1, 0);
    cudaEventRecord(evG1, s1);
    cudaStreamWaitEvent(0, evG1, 0);

    // ---- layer 2 ----
    agg_kernel<<<MSPLIT, 128>>>(h1, Ahi, Alo, 0);
    cudaEventRecord(evA2, 0);
    cudaStreamWaitEvent(s1, evA2, 0);
    agg_kernel<<<NN - MSPLIT, 128, 0, s1>>>(h1, Ahi, Alo, MSPLIT);
    gemm_mma<<<gridA, 256, GEMM_SMEM>>>(Ahi, Alo, W2h, b2, h2,
                                        nullptr, nullptr, nullptr, 0, NN, 1, 0);
    gemm_mma<<<gridB, 256, GEMM_SMEM, s1>>>(Ahi, Alo, W2h, b2, h2,
                                            nullptr, nullptr, nullptr, MSPLIT, NN, 1, 0);
    cudaEventRecord(evG2, s1);
    cudaStreamWaitEvent(0, evG2, 0);

    // ---- layer 3: shared agg feeds h3 (W2,relu) and h4 (W3) in one dual GEMM ----
    agg_kernel<<<MSPLIT, 128>>>(h2, Ahi, Alo, 0);
    cudaEventRecord(evA3, 0);
    cudaStreamWaitEvent(s1, evA3, 0);
    agg_kernel<<<NN - MSPLIT, 128, 0, s1>>>(h2, Ahi, Alo, MSPLIT);
    gemm_mma<<<gridA2, 256, GEMM_SMEM>>>(Ahi, Alo, W2h, b2, h3, W3h, b3, h4, 0, NN, 1, 1);
    gemm_mma<<<gridB2, 256, GEMM_SMEM, s1>>>(Ahi, Alo, W2h, b2, h3, W3h, b3, h4, MSPLIT, NN, 1, 1);
    cudaEventRecord(evG3, s1);
    cudaStreamWaitEvent(0, evG3, 0);
}

// round 7
// speedup vs baseline: 4.3477x; 1.0208x over previous
#include <cuda_runtime.h>
#include <cuda_fp16.h>
#include <cstdint>

#define NN 10000
#define NE 160000
#define F 512
#define MSPLIT 5120
#define MA_BLK 40
#define MB_BLK 39

// ==================== scratch (device globals) ====================
__device__ int   g_ivec[3][NN];     // [0]=deg_out [1]=deg_in [2]=cnt (one memset)
#define g_deg_out (g_ivec[0])
#define g_deg_in  (g_ivec[1])
#define g_cnt     (g_ivec[2])
__device__ int   g_off[NN + 1];
__device__ int   g_csr_src[NE];
__device__ float g_csr_w[NE];
__device__ __half g_x16[(size_t)NN * F];    // fp16 features: x, later reused for h2
__device__ __half g_hf16[(size_t)NN * F];   // fp16 h1
__device__ __half g_Ahi[(size_t)NN * F];
__device__ __half g_Alo[(size_t)NN * F];
__device__ __half g_W1h[F * F], g_W2h[F * F], g_W3h[F * F];

// ==================== PTX helpers ====================
__device__ __forceinline__ uint32_t smem_to_u32(const void* p) {
    uint32_t a;
    asm("{ .reg .u64 t; cvta.to.shared.u64 t, %1; cvt.u32.u64 %0, t; }" : "=r"(a) : "l"(p));
    return a;
}
__device__ __forceinline__ void cp_async16(uint32_t dst, const void* src, int sz) {
    asm volatile("cp.async.cg.shared.global [%0], [%1], 16, %2;"
        :: "r"(dst), "l"(src), "r"(sz) : "memory");
}
__device__ __forceinline__ void ldsm4(uint32_t* r, uint32_t addr) {
    asm volatile("ldmatrix.sync.aligned.m8n8.x4.shared.b16 {%0,%1,%2,%3}, [%4];"
        : "=r"(r[0]), "=r"(r[1]), "=r"(r[2]), "=r"(r[3]) : "r"(addr));
}
__device__ __forceinline__ void mma_f16(float* d, const uint32_t* a, const uint32_t* b) {
    asm volatile(
        "mma.sync.aligned.m16n8k16.row.col.f32.f16.f16.f32 "
        "{%0,%1,%2,%3}, {%4,%5,%6,%7}, {%8,%9}, {%0,%1,%2,%3};"
        : "+f"(d[0]), "+f"(d[1]), "+f"(d[2]), "+f"(d[3])
        : "r"(a[0]), "r"(a[1]), "r"(a[2]), "r"(a[3]), "r"(b[0]), "r"(b[1]));
}

// ==================== setup kernels ====================
__global__ void degree_kernel(const int* __restrict__ src, const int* __restrict__ dst) {
    int e = blockIdx.x * blockDim.x + threadIdx.x;
    if (e < NE) {
        atomicAdd(&g_deg_out[src[e]], 1);
        atomicAdd(&g_deg_in[dst[e]], 1);
    }
}

// exclusive scan of g_deg_in -> g_off; 1024 threads x 12 elems (int4 x3)
__global__ void scan_kernel() {
    __shared__ int wsum[32];
    int tid = threadIdx.x;
    const int4* din4 = reinterpret_cast<const int4*>(g_deg_in);  // spills into zeroed cnt
    int v[12];
    #pragma unroll
    for (int j = 0; j < 3; ++j) {
        int4 q = din4[tid * 3 + j];
        v[j * 4 + 0] = q.x; v[j * 4 + 1] = q.y; v[j * 4 + 2] = q.z; v[j * 4 + 3] = q.w;
    }
    int loc[12];
    int s = 0;
    #pragma unroll
    for (int i = 0; i < 12; ++i) { loc[i] = s; s += v[i]; }
    int x = s;
    #pragma unroll
    for (int d = 1; d < 32; d <<= 1) {
        int y = __shfl_up_sync(0xffffffffu, x, d);
        if ((tid & 31) >= d) x += y;
    }
    if ((tid & 31) == 31) wsum[tid >> 5] = x;
    __syncthreads();
    if (tid < 32) {
        int w = wsum[tid];
        #pragma unroll
        for (int d = 1; d < 32; d <<= 1) {
            int y = __shfl_up_sync(0xffffffffu, w, d);
            if (tid >= d) w += y;
        }
        wsum[tid] = w;
    }
    __syncthreads();
    int pref = x - s + ((tid >= 32) ? wsum[(tid >> 5) - 1] : 0);
    int base = tid * 12;
    #pragma unroll
    for (int i = 0; i < 12; ++i) {
        int idx = base + i;
        if (idx < NN) g_off[idx] = pref + loc[i];
    }
    if (tid == 1023) g_off[NN] = pref + s;
}

__global__ void scatter_kernel(const int* __restrict__ src, const int* __restrict__ dst) {
    int e = blockIdx.x * blockDim.x + threadIdx.x;
    if (e < NE) {
        int d = dst[e];
        int pos = g_off[d] + atomicAdd(&g_cnt[d], 1);
        int s = src[e];
        g_csr_src[pos] = s;
        g_csr_w[pos]   = rsqrtf((float)g_deg_out[s]);
    }
}

// x fp32 -> fp16 (row layout preserved)
__global__ void xconvert_kernel(const float* __restrict__ x, __half* __restrict__ o) {
    int i = blockIdx.x * blockDim.x + threadIdx.x;   // one float4 -> half2x2
    float4 v = reinterpret_cast<const float4*>(x)[i];
    __half2 a = __floats2half2_rn(v.x, v.y);
    __half2 b = __floats2half2_rn(v.z, v.w);
    uint32_t ua = *reinterpret_cast<uint32_t*>(&a);
    uint32_t ub = *reinterpret_cast<uint32_t*>(&b);
    reinterpret_cast<uint2*>(o)[i] = make_uint2(ua, ub);
}

// all three W k-major -> transposed fp16 Wt[n][k]
__global__ void wsplit3_kernel(const float* __restrict__ W1, const float* __restrict__ W2,
                               const float* __restrict__ W3,
                               __half* __restrict__ O1, __half* __restrict__ O2,
                               __half* __restrict__ O3) {
    const float* W = (blockIdx.z == 0) ? W1 : (blockIdx.z == 1) ? W2 : W3;
    __half* Oh = (blockIdx.z == 0) ? O1 : (blockIdx.z == 1) ? O2 : O3;
    __shared__ float t[32][33];
    int n = blockIdx.x * 32 + threadIdx.x;
    int k = blockIdx.y * 32 + threadIdx.y;
    t[threadIdx.y][threadIdx.x] = W[(size_t)k * F + n];
    __syncthreads();
    int on = blockIdx.x * 32 + threadIdx.y;
    int ok = blockIdx.y * 32 + threadIdx.x;
    Oh[(size_t)on * F + ok] = __float2half_rn(t[threadIdx.x][threadIdx.y]);
}

// ==================== aggregation (fp16 gather, fp32 accumulate) ====================
// 128 threads, 4 features each (uint2 = 4 halves)
__global__ __launch_bounds__(128) void agg_kernel(const __half* __restrict__ x,
                                                  __half* __restrict__ ohi,
                                                  __half* __restrict__ olo,
                                                  int nodeBase) {
    int node = nodeBase + blockIdx.x;
    int tid  = threadIdx.x;
    int beg = g_off[node];
    int end = g_off[node + 1];
    const uint2* x2 = reinterpret_cast<const uint2*>(x);   // row stride 128 uint2
    float4 acc = make_float4(0.f, 0.f, 0.f, 0.f);
    int i = beg;
    for (; i + 4 <= end; i += 4) {
        int   s0 = __ldg(&g_csr_src[i + 0]);
        int   s1 = __ldg(&g_csr_src[i + 1]);
        int   s2 = __ldg(&g_csr_src[i + 2]);
        int   s3 = __ldg(&g_csr_src[i + 3]);
        float w0 = __ldg(&g_csr_w[i + 0]);
        float w1 = __ldg(&g_csr_w[i + 1]);
        float w2 = __ldg(&g_csr_w[i + 2]);
        float w3 = __ldg(&g_csr_w[i + 3]);
        uint2 u0 = x2[(size_t)s0 * 128 + tid];
        uint2 u1 = x2[(size_t)s1 * 128 + tid];
        uint2 u2 = x2[(size_t)s2 * 128 + tid];
        uint2 u3 = x2[(size_t)s3 * 128 + tid];
        float2 a0 = __half22float2(*reinterpret_cast<__half2*>(&u0.x));
        float2 b0 = __half22float2(*reinterpret_cast<__half2*>(&u0.y));
        float2 a1 = __half22float2(*reinterpret_cast<__half2*>(&u1.x));
        float2 b1 = __half22float2(*reinterpret_cast<__half2*>(&u1.y));
        float2 a2 = __half22float2(*reinterpret_cast<__half2*>(&u2.x));
        float2 b2 = __half22float2(*reinterpret_cast<__half2*>(&u2.y));
        float2 a3 = __half22float2(*reinterpret_cast<__half2*>(&u3.x));
        float2 b3 = __half22float2(*reinterpret_cast<__half2*>(&u3.y));
        acc.x = fmaf(w0, a0.x, acc.x); acc.y = fmaf(w0, a0.y, acc.y);
        acc.z = fmaf(w0, b0.x, acc.z); acc.w = fmaf(w0, b0.y, acc.w);
        acc.x = fmaf(w1, a1.x, acc.x); acc.y = fmaf(w1, a1.y, acc.y);
        acc.z = fmaf(w1, b1.x, acc.z); acc.w = fmaf(w1, b1.y, acc.w);
        acc.x = fmaf(w2, a2.x, acc.x); acc.y = fmaf(w2, a2.y, acc.y);
        acc.z = fmaf(w2, b2.x, acc.z); acc.w = fmaf(w2, b2.y, acc.w);
        acc.x = fmaf(w3, a3.x, acc.x); acc.y = fmaf(w3, a3.y, acc.y);
        acc.z = fmaf(w3, b3.x, acc.z); acc.w = fmaf(w3, b3.y, acc.w);
    }
    for (; i < end; ++i) {
        int   s = __ldg(&g_csr_src[i]);
        float w = __ldg(&g_csr_w[i]);
        uint2 u = x2[(size_t)s * 128 + tid];
        float2 a = __half22float2(*reinterpret_cast<__half2*>(&u.x));
        float2 b = __half22float2(*reinterpret_cast<__half2*>(&u.y));
        acc.x = fmaf(w, a.x, acc.x); acc.y = fmaf(w, a.y, acc.y);
        acc.z = fmaf(w, b.x, acc.z); acc.w = fmaf(w, b.y, acc.w);
    }
    float ni = (end > beg) ? rsqrtf((float)(end - beg)) : 0.f;
    float r[4] = {acc.x * ni, acc.y * ni, acc.z * ni, acc.w * ni};
    unsigned short hb[4], lb[4];
    #pragma unroll
    for (int j = 0; j < 4; ++j) {
        __half h = __float2half_rn(r[j]);
        float hf = __half2float(h);
        __half l = __float2half_rn(r[j] - hf);
        hb[j] = __half_as_ushort(h);
        lb[j] = __half_as_ushort(l);
    }
    uint2 uh = make_uint2((uint32_t)hb[0] | ((uint32_t)hb[1] << 16),
                          (uint32_t)hb[2] | ((uint32_t)hb[3] << 16));
    uint2 ul = make_uint2((uint32_t)lb[0] | ((uint32_t)lb[1] << 16),
                          (uint32_t)lb[2] | ((uint32_t)lb[3] << 16));
    reinterpret_cast<uint2*>(ohi + (size_t)node * F)[tid] = uh;
    reinterpret_cast<uint2*>(olo + (size_t)node * F)[tid] = ul;
}

// ==================== mma.sync GEMM: C = (Ah+Al)@B^T + bias ====================
// Outputs: optional fp32 C and/or fp16 C16.
#define STAGE_BYTES 40960
#define GEMM_SMEM (2 * STAGE_BYTES)

__device__ __forceinline__ void load_stage(
    uint32_t s, int m0, int n0, int M, int k0, int tid,
    const __half* __restrict__ Ah, const __half* __restrict__ Al,
    const __half* __restrict__ B)
{
    #pragma unroll
    for (int i = 0; i < 4; ++i) {
        int v = tid + i * 256;
        int row = v >> 3, c = v & 7;
        uint32_t phys = (uint32_t)(row * 128 + ((c ^ (row & 7)) << 4));
        size_t g = (size_t)(m0 + row) * F + k0 + c * 8;
        int sz = (m0 + row < M) ? 16 : 0;
        cp_async16(s + phys, Ah + g, sz);
        cp_async16(s + 16384 + phys, Al + g, sz);
    }
    #pragma unroll
    for (int i = 0; i < 2; ++i) {
        int v = tid + i * 256;
        int row = v >> 3, c = v & 7;
        uint32_t phys = (uint32_t)(row * 128 + ((c ^ (row & 7)) << 4));
        size_t g = (size_t)(n0 + row) * F + k0 + c * 8;
        cp_async16(s + 32768 + phys, B + g, 16);
    }
    asm volatile("cp.async.commit_group;" ::: "memory");
}

__global__ __launch_bounds__(256, 2) void gemm_mma(
    const __half* __restrict__ Ah, const __half* __restrict__ Al,
    const __half* __restrict__ B, const float* __restrict__ bias,
    float* __restrict__ C, __half* __restrict__ C16,
    const __half* __restrict__ B2, const float* __restrict__ bias2, float* __restrict__ C2,
    int mBase, int M, int relu, int dual)
{
    extern __shared__ char smem[];
    const uint32_t sb = smem_to_u32(smem);
    const int tid = threadIdx.x;
    const int wid = tid >> 5, lid = tid & 31;
    int nb = blockIdx.x;
    if (dual && nb >= 8) {
        nb -= 8;
        B = B2; bias = bias2; C = C2; C16 = nullptr; relu = 0;
    }
    const int m0 = mBase + blockIdx.y * 128, n0 = nb * 64;
    const int wm = (wid >> 1) * 32;
    const int wn = (wid & 1) * 32;

    float acc[2][4][4];
    #pragma unroll
    for (int a = 0; a < 2; ++a)
        #pragma unroll
        for (int b = 0; b < 4; ++b)
            #pragma unroll
            for (int c = 0; c < 4; ++c) acc[a][b][c] = 0.f;

    load_stage(sb, m0, n0, M, 0, tid, Ah, Al, B);
    load_stage(sb + STAGE_BYTES, m0, n0, M, 64, tid, Ah, Al, B);

    const int NCH = F / 64;   // 8
    for (int ch = 0; ch < NCH; ++ch) {
        asm volatile("cp.async.wait_group 1;" ::: "memory");
        __syncthreads();
        const uint32_t s = sb + (ch & 1) * STAGE_BYTES;

        #pragma unroll
        for (int kk = 0; kk < 4; ++kk) {
            uint32_t ahf[2][4], alf[2][4];
            #pragma unroll
            for (int mt = 0; mt < 2; ++mt) {
                int row = wm + mt * 16 + (lid & 15);
                int c = kk * 2 + ((lid >> 4) & 1);
                uint32_t ad = s + row * 128 + ((c ^ (row & 7)) << 4);
                ldsm4(ahf[mt], ad);
                ldsm4(alf[mt], ad + 16384);
            }
            #pragma unroll
            for (int p = 0; p < 2; ++p) {
                int row = wn + p * 16 + (lid & 7) + (((lid >> 4) & 1) << 3);
                int c = kk * 2 + ((lid >> 3) & 1);
                uint32_t bd = s + 32768 + row * 128 + ((c ^ (row & 7)) << 4);
                uint32_t bf[4];
                ldsm4(bf, bd);
                #pragma unroll
                for (int mt = 0; mt < 2; ++mt) {
                    mma_f16(acc[mt][2 * p],     ahf[mt], bf);
                    mma_f16(acc[mt][2 * p],     alf[mt], bf);
                    mma_f16(acc[mt][2 * p + 1], ahf[mt], bf + 2);
                    mma_f16(acc[mt][2 * p + 1], alf[mt], bf + 2);
                }
            }
        }
        __syncthreads();
        if (ch + 2 < NCH)
            load_stage(sb + (ch & 1) * STAGE_BYTES, m0, n0, M, (ch + 2) * 64, tid, Ah, Al, B);
        else
            asm volatile("cp.async.commit_group;" ::: "memory");
    }

    #pragma unroll
    for (int mt = 0; mt < 2; ++mt) {
        int rbase = m0 + wm + mt * 16 + (lid >> 2);
        #pragma unroll
        for (int half = 0; half < 2; ++half) {
            int m = rbase + half * 8;
            if (m < M) {
                #pragma unroll
                for (int nt = 0; nt < 4; ++nt) {
                    int n = n0 + wn + nt * 8 + (lid & 3) * 2;
                    float2 o;
                    o.x = acc[mt][nt][half * 2 + 0] + bias[n];
                    o.y = acc[mt][nt][half * 2 + 1] + bias[n + 1];
                    if (relu) { o.x = fmaxf(o.x, 0.f); o.y = fmaxf(o.y, 0.f); }
                    if (C)
                        *reinterpret_cast<float2*>(C + (size_t)m * F + n) = o;
                    if (C16) {
                        __half2 h = __floats2half2_rn(o.x, o.y);
                        *reinterpret_cast<__half2*>(C16 + (size_t)m * F + n) = h;
                    }
                }
            }
        }
    }
}

// ==================== launcher ====================
extern "C" void kernel_launch(void* const* d_in, const int* in_sizes, int n_in,
                              void* d_out, int out_size) {
    const float* x   = (const float*)d_in[0];
    const float* W1  = (const float*)d_in[1];
    const float* b1  = (const float*)d_in[2];
    const float* W2  = (const float*)d_in[3];
    const float* b2  = (const float*)d_in[4];
    const float* W3  = (const float*)d_in[5];
    const float* b3  = (const float*)d_in[6];
    const int*   src = (const int*)d_in[7];
    const int*   dst = (const int*)d_in[8];

    float* out = (float*)d_out;
    float* h4 = out;
    float* h3 = out + (size_t)NN * F;
    float* h2 = out + 2 * (size_t)NN * F;

    void* ivec = nullptr;
    __half *x16 = nullptr, *hf16 = nullptr, *Ahi = nullptr, *Alo = nullptr;
    __half *W1h = nullptr, *W2h = nullptr, *W3h = nullptr;
    cudaGetSymbolAddress(&ivec, g_ivec);
    cudaGetSymbolAddress((void**)&x16,  g_x16);
    cudaGetSymbolAddress((void**)&hf16, g_hf16);
    cudaGetSymbolAddress((void**)&Ahi, g_Ahi);
    cudaGetSymbolAddress((void**)&Alo, g_Alo);
    cudaGetSymbolAddress((void**)&W1h, g_W1h);
    cudaGetSymbolAddress((void**)&W2h, g_W2h);
    cudaGetSymbolAddress((void**)&W3h, g_W3h);

    cudaFuncSetAttribute(gemm_mma, cudaFuncAttributeMaxDynamicSharedMemorySize, GEMM_SMEM);

    cudaStream_t s1;
    cudaStreamCreateWithFlags(&s1, cudaStreamNonBlocking);
    cudaEvent_t evFork, evX, evA1, evA2, evA3, evG1, evG2, evG3;
    cudaEventCreateWithFlags(&evFork, cudaEventDisableTiming);
    cudaEventCreateWithFlags(&evX,  cudaEventDisableTiming);
    cudaEventCreateWithFlags(&evA1, cudaEventDisableTiming);
    cudaEventCreateWithFlags(&evA2, cudaEventDisableTiming);
    cudaEventCreateWithFlags(&evA3, cudaEventDisableTiming);
    cudaEventCreateWithFlags(&evG1, cudaEventDisableTiming);
    cudaEventCreateWithFlags(&evG2, cudaEventDisableTiming);
    cudaEventCreateWithFlags(&evG3, cudaEventDisableTiming);

    // side stream: x->fp16 convert + weight transpose/quantize, all off critical path
    cudaEventRecord(evFork, 0);
    cudaStreamWaitEvent(s1, evFork, 0);
    xconvert_kernel<<<(NN * F / 4 + 255) / 256, 256, 0, s1>>>(x, x16);
    wsplit3_kernel<<<dim3(16, 16, 3), dim3(32, 32), 0, s1>>>(W1, W2, W3, W1h, W2h, W3h);
    cudaEventRecord(evX, s1);

    const int TB = 256;
    cudaMemsetAsync(ivec, 0, sizeof(int) * 3 * NN, 0);
    degree_kernel<<<(NE + TB - 1) / TB, TB>>>(src, dst);
    scan_kernel<<<1, 1024>>>();
    scatter_kernel<<<(NE + TB - 1) / TB, TB>>>(src, dst);
    cudaStreamWaitEvent(0, evX, 0);    // x16 + weights ready

    dim3 gridA(8, MA_BLK), gridB(8, MB_BLK);
    dim3 gridA2(16, MA_BLK), gridB2(16, MB_BLK);

    // ---- layer 1: h1 (fp16 only) ----
    agg_kernel<<<MSPLIT, 128>>>(x16, Ahi, Alo, 0);
    cudaEventRecord(evA1, 0);
    cudaStreamWaitEvent(s1, evA1, 0);
    agg_kernel<<<NN - MSPLIT, 128, 0, s1>>>(x16, Ahi, Alo, MSPLIT);
    gemm_mma<<<gridA, 256, GEMM_SMEM>>>(Ahi, Alo, W1h, b1, nullptr, hf16,
                                        nullptr, nullptr, nullptr, 0, NN, 1, 0);
    gemm_mma<<<gridB, 256, GEMM_SMEM, s1>>>(Ahi, Alo, W1h, b1, nullptr, hf16,
                                            nullptr, nullptr, nullptr, MSPLIT, NN, 1, 0);
    cudaEventRecord(evG1, s1);
    cudaStreamWaitEvent(0, evG1, 0);

    // ---- layer 2: h2 (fp32 to d_out + fp16 copy into x16) ----
    agg_kernel<<<MSPLIT, 128>>>(hf16, Ahi, Alo, 0);
    cudaEventRecord(evA2, 0);
    cudaStreamWaitEvent(s1, evA2, 0);
    agg_kernel<<<NN - MSPLIT, 128, 0, s1>>>(hf16, Ahi, Alo, MSPLIT);
    gemm_mma<<<gridA, 256, GEMM_SMEM>>>(Ahi, Alo, W2h, b2, h2, x16,
                                        nullptr, nullptr, nullptr, 0, NN, 1, 0);
    gemm_mma<<<gridB, 256, GEMM_SMEM, s1>>>(Ahi, Alo, W2h, b2, h2, x16,
                                            nullptr, nullptr, nullptr, MSPLIT, NN, 1, 0);
    cudaEventRecord(evG2, s1);
    cudaStreamWaitEvent(0, evG2, 0);

    // ---- layer 3: shared agg feeds h3 (W2,relu) and h4 (W3) in one dual GEMM ----
    agg_kernel<<<MSPLIT, 128>>>(x16, Ahi, Alo, 0);
    cudaEventRecord(evA3, 0);
    cudaStreamWaitEvent(s1, evA3, 0);
    agg_kernel<<<NN - MSPLIT, 128, 0, s1>>>(x16, Ahi, Alo, MSPLIT);
    gemm_mma<<<gridA2, 256, GEMM_SMEM>>>(Ahi, Alo, W2h, b2, h3, nullptr,
                                         W3h, b3, h4, 0, NN, 1, 1);
    gemm_mma<<<gridB2, 256, GEMM_SMEM, s1>>>(Ahi, Alo, W2h, b2, h3, nullptr,
                                             W3h, b3, h4, MSPLIT, NN, 1, 1);
    cudaEventRecord(evG3, s1);
    cudaStreamWaitEvent(0, evG3, 0);
}

// round 8
// speedup vs baseline: 5.8188x; 1.3384x over previous
#include <cuda_runtime.h>
#include <cuda_fp16.h>
#include <cstdint>

#define NN 10000
#define NE 160000
#define F 512

// ==================== scratch (device globals) ====================
__device__ int   g_ivec[3][NN];     // [0]=deg_out [1]=deg_in [2]=cnt (one memset)
#define g_deg_out (g_ivec[0])
#define g_deg_in  (g_ivec[1])
#define g_cnt     (g_ivec[2])
__device__ int   g_off[NN + 1];
__device__ int   g_csr_src[NE];
__device__ float g_csr_w[NE];
__device__ __half g_x16[(size_t)NN * F];    // fp16 features: x, later h2
__device__ __half g_hf16[(size_t)NN * F];   // fp16 h1
__device__ __half g_A16[(size_t)NN * F];    // aggregated fp16 (GEMM A operand)
__device__ __half g_W1h[F * F], g_W2h[F * F], g_W3h[F * F];

// ==================== PTX helpers ====================
__device__ __forceinline__ uint32_t smem_to_u32(const void* p) {
    uint32_t a;
    asm("{ .reg .u64 t; cvta.to.shared.u64 t, %1; cvt.u32.u64 %0, t; }" : "=r"(a) : "l"(p));
    return a;
}
__device__ __forceinline__ void cp_async16(uint32_t dst, const void* src, int sz) {
    asm volatile("cp.async.cg.shared.global [%0], [%1], 16, %2;"
        :: "r"(dst), "l"(src), "r"(sz) : "memory");
}
__device__ __forceinline__ void ldsm4(uint32_t* r, uint32_t addr) {
    asm volatile("ldmatrix.sync.aligned.m8n8.x4.shared.b16 {%0,%1,%2,%3}, [%4];"
        : "=r"(r[0]), "=r"(r[1]), "=r"(r[2]), "=r"(r[3]) : "r"(addr));
}
__device__ __forceinline__ void mma_f16(float* d, const uint32_t* a, const uint32_t* b) {
    asm volatile(
        "mma.sync.aligned.m16n8k16.row.col.f32.f16.f16.f32 "
        "{%0,%1,%2,%3}, {%4,%5,%6,%7}, {%8,%9}, {%0,%1,%2,%3};"
        : "+f"(d[0]), "+f"(d[1]), "+f"(d[2]), "+f"(d[3])
        : "r"(a[0]), "r"(a[1]), "r"(a[2]), "r"(a[3]), "r"(b[0]), "r"(b[1]));
}

// ==================== setup kernels ====================
__global__ void degree_kernel(const int* __restrict__ src, const int* __restrict__ dst) {
    int e = blockIdx.x * blockDim.x + threadIdx.x;
    if (e < NE) {
        atomicAdd(&g_deg_out[src[e]], 1);
        atomicAdd(&g_deg_in[dst[e]], 1);
    }
}

// exclusive scan of g_deg_in -> g_off; 1024 threads x 12 elems (int4 x3)
__global__ void scan_kernel() {
    __shared__ int wsum[32];
    int tid = threadIdx.x;
    const int4* din4 = reinterpret_cast<const int4*>(g_deg_in);  // spills into zeroed cnt
    int v[12];
    #pragma unroll
    for (int j = 0; j < 3; ++j) {
        int4 q = din4[tid * 3 + j];
        v[j * 4 + 0] = q.x; v[j * 4 + 1] = q.y; v[j * 4 + 2] = q.z; v[j * 4 + 3] = q.w;
    }
    int loc[12];
    int s = 0;
    #pragma unroll
    for (int i = 0; i < 12; ++i) { loc[i] = s; s += v[i]; }
    int x = s;
    #pragma unroll
    for (int d = 1; d < 32; d <<= 1) {
        int y = __shfl_up_sync(0xffffffffu, x, d);
        if ((tid & 31) >= d) x += y;
    }
    if ((tid & 31) == 31) wsum[tid >> 5] = x;
    __syncthreads();
    if (tid < 32) {
        int w = wsum[tid];
        #pragma unroll
        for (int d = 1; d < 32; d <<= 1) {
            int y = __shfl_up_sync(0xffffffffu, w, d);
            if (tid >= d) w += y;
        }
        wsum[tid] = w;
    }
    __syncthreads();
    int pref = x - s + ((tid >= 32) ? wsum[(tid >> 5) - 1] : 0);
    int base = tid * 12;
    #pragma unroll
    for (int i = 0; i < 12; ++i) {
        int idx = base + i;
        if (idx < NN) g_off[idx] = pref + loc[i];
    }
    if (tid == 1023) g_off[NN] = pref + s;
}

__global__ void scatter_kernel(const int* __restrict__ src, const int* __restrict__ dst) {
    int e = blockIdx.x * blockDim.x + threadIdx.x;
    if (e < NE) {
        int d = dst[e];
        int pos = g_off[d] + atomicAdd(&g_cnt[d], 1);
        int s = src[e];
        g_csr_src[pos] = s;
        g_csr_w[pos]   = rsqrtf((float)g_deg_out[s]);
    }
}

// x fp32 -> fp16
__global__ void xconvert_kernel(const float* __restrict__ x, __half* __restrict__ o) {
    int i = blockIdx.x * blockDim.x + threadIdx.x;
    float4 v = reinterpret_cast<const float4*>(x)[i];
    __half2 a = __floats2half2_rn(v.x, v.y);
    __half2 b = __floats2half2_rn(v.z, v.w);
    uint32_t ua = *reinterpret_cast<uint32_t*>(&a);
    uint32_t ub = *reinterpret_cast<uint32_t*>(&b);
    reinterpret_cast<uint2*>(o)[i] = make_uint2(ua, ub);
}

// all three W k-major -> transposed fp16 Wt[n][k]
__global__ void wsplit3_kernel(const float* __restrict__ W1, const float* __restrict__ W2,
                               const float* __restrict__ W3,
                               __half* __restrict__ O1, __half* __restrict__ O2,
                               __half* __restrict__ O3) {
    const float* W = (blockIdx.z == 0) ? W1 : (blockIdx.z == 1) ? W2 : W3;
    __half* Oh = (blockIdx.z == 0) ? O1 : (blockIdx.z == 1) ? O2 : O3;
    __shared__ float t[32][33];
    int n = blockIdx.x * 32 + threadIdx.x;
    int k = blockIdx.y * 32 + threadIdx.y;
    t[threadIdx.y][threadIdx.x] = W[(size_t)k * F + n];
    __syncthreads();
    int on = blockIdx.x * 32 + threadIdx.y;
    int ok = blockIdx.y * 32 + threadIdx.x;
    Oh[(size_t)on * F + ok] = __float2half_rn(t[threadIdx.x][threadIdx.y]);
}

// ==================== aggregation (fp16 gather, fp32 accumulate, fp16 out) ====================
__global__ __launch_bounds__(128) void agg_kernel(const __half* __restrict__ x,
                                                  __half* __restrict__ o) {
    int node = blockIdx.x;
    int tid  = threadIdx.x;
    int beg = g_off[node];
    int end = g_off[node + 1];
    const uint2* x2 = reinterpret_cast<const uint2*>(x);   // row stride 128 uint2
    float4 acc = make_float4(0.f, 0.f, 0.f, 0.f);
    int i = beg;
    for (; i + 4 <= end; i += 4) {
        int   s0 = __ldg(&g_csr_src[i + 0]);
        int   s1 = __ldg(&g_csr_src[i + 1]);
        int   s2 = __ldg(&g_csr_src[i + 2]);
        int   s3 = __ldg(&g_csr_src[i + 3]);
        float w0 = __ldg(&g_csr_w[i + 0]);
        float w1 = __ldg(&g_csr_w[i + 1]);
        float w2 = __ldg(&g_csr_w[i + 2]);
        float w3 = __ldg(&g_csr_w[i + 3]);
        uint2 u0 = x2[(size_t)s0 * 128 + tid];
        uint2 u1 = x2[(size_t)s1 * 128 + tid];
        uint2 u2 = x2[(size_t)s2 * 128 + tid];
        uint2 u3 = x2[(size_t)s3 * 128 + tid];
        float2 a0 = __half22float2(*reinterpret_cast<__half2*>(&u0.x));
        float2 b0 = __half22float2(*reinterpret_cast<__half2*>(&u0.y));
        float2 a1 = __half22float2(*reinterpret_cast<__half2*>(&u1.x));
        float2 b1 = __half22float2(*reinterpret_cast<__half2*>(&u1.y));
        float2 a2 = __half22float2(*reinterpret_cast<__half2*>(&u2.x));
        float2 b2 = __half22float2(*reinterpret_cast<__half2*>(&u2.y));
        float2 a3 = __half22float2(*reinterpret_cast<__half2*>(&u3.x));
        float2 b3 = __half22float2(*reinterpret_cast<__half2*>(&u3.y));
        acc.x = fmaf(w0, a0.x, acc.x); acc.y = fmaf(w0, a0.y, acc.y);
        acc.z = fmaf(w0, b0.x, acc.z); acc.w = fmaf(w0, b0.y, acc.w);
        acc.x = fmaf(w1, a1.x, acc.x); acc.y = fmaf(w1, a1.y, acc.y);
        acc.z = fmaf(w1, b1.x, acc.z); acc.w = fmaf(w1, b1.y, acc.w);
        acc.x = fmaf(w2, a2.x, acc.x); acc.y = fmaf(w2, a2.y, acc.y);
        acc.z = fmaf(w2, b2.x, acc.z); acc.w = fmaf(w2, b2.y, acc.w);
        acc.x = fmaf(w3, a3.x, acc.x); acc.y = fmaf(w3, a3.y, acc.y);
        acc.z = fmaf(w3, b3.x, acc.z); acc.w = fmaf(w3, b3.y, acc.w);
    }
    for (; i < end; ++i) {
        int   s = __ldg(&g_csr_src[i]);
        float w = __ldg(&g_csr_w[i]);
        uint2 u = x2[(size_t)s * 128 + tid];
        float2 a = __half22float2(*reinterpret_cast<__half2*>(&u.x));
        float2 b = __half22float2(*reinterpret_cast<__half2*>(&u.y));
        acc.x = fmaf(w, a.x, acc.x); acc.y = fmaf(w, a.y, acc.y);
        acc.z = fmaf(w, b.x, acc.z); acc.w = fmaf(w, b.y, acc.w);
    }
    float ni = (end > beg) ? rsqrtf((float)(end - beg)) : 0.f;
    __half2 p0 = __floats2half2_rn(acc.x * ni, acc.y * ni);
    __half2 p1 = __floats2half2_rn(acc.z * ni, acc.w * ni);
    uint2 u = make_uint2(*reinterpret_cast<uint32_t*>(&p0), *reinterpret_cast<uint32_t*>(&p1));
    reinterpret_cast<uint2*>(o + (size_t)node * F)[tid] = u;
}

// ==================== mma.sync GEMM: C = A@B^T + bias (single fp16 A) ====================
// CTA 128x128, 256 thr (8 warps, warp tile 32x64), BK=64, double buffer.
// Stage (32KB): A[0,16K) B[16K,32K). Rows 128B, 16B chunk c at row r -> c^(r&7).
#define STAGE_BYTES 32768
#define GEMM_SMEM (2 * STAGE_BYTES)

__device__ __forceinline__ void load_stage(
    uint32_t s, int m0, int n0, int M, int k0, int tid,
    const __half* __restrict__ A, const __half* __restrict__ B)
{
    #pragma unroll
    for (int i = 0; i < 4; ++i) {
        int v = tid + i * 256;        // 0..1023
        int row = v >> 3, c = v & 7;
        uint32_t phys = (uint32_t)(row * 128 + ((c ^ (row & 7)) << 4));
        size_t gA = (size_t)(m0 + row) * F + k0 + c * 8;
        int sz = (m0 + row < M) ? 16 : 0;
        cp_async16(s + phys, A + gA, sz);
        size_t gB = (size_t)(n0 + row) * F + k0 + c * 8;
        cp_async16(s + 16384 + phys, B + gB, 16);
    }
    asm volatile("cp.async.commit_group;" ::: "memory");
}

// dual=0: grid.x=4; dual=1: grid.x=8, high 4 -> (B2,bias2,C2,no relu)
__global__ __launch_bounds__(256, 2) void gemm_mma(
    const __half* __restrict__ A,
    const __half* __restrict__ B, const float* __restrict__ bias,
    float* __restrict__ C, __half* __restrict__ C16,
    const __half* __restrict__ B2, const float* __restrict__ bias2, float* __restrict__ C2,
    int M, int relu, int dual)
{
    extern __shared__ char smem[];
    const uint32_t sb = smem_to_u32(smem);
    const int tid = threadIdx.x;
    const int wid = tid >> 5, lid = tid & 31;
    int nb = blockIdx.x;
    if (dual && nb >= 4) {
        nb -= 4;
        B = B2; bias = bias2; C = C2; C16 = nullptr; relu = 0;
    }
    const int m0 = blockIdx.y * 128, n0 = nb * 128;
    const int wm = (wid & 3) * 32;
    const int wn = (wid >> 2) * 64;

    float acc[2][8][4];
    #pragma unroll
    for (int a = 0; a < 2; ++a)
        #pragma unroll
        for (int b = 0; b < 8; ++b)
            #pragma unroll
            for (int c = 0; c < 4; ++c) acc[a][b][c] = 0.f;

    load_stage(sb, m0, n0, M, 0, tid, A, B);
    load_stage(sb + STAGE_BYTES, m0, n0, M, 64, tid, A, B);

    const int NCH = F / 64;   // 8
    for (int ch = 0; ch < NCH; ++ch) {
        asm volatile("cp.async.wait_group 1;" ::: "memory");
        __syncthreads();
        const uint32_t s = sb + (ch & 1) * STAGE_BYTES;

        #pragma unroll
        for (int kk = 0; kk < 4; ++kk) {
            uint32_t af[2][4];
            #pragma unroll
            for (int mt = 0; mt < 2; ++mt) {
                int row = wm + mt * 16 + (lid & 15);
                int c = kk * 2 + ((lid >> 4) & 1);
                ldsm4(af[mt], s + row * 128 + ((c ^ (row & 7)) << 4));
            }
            #pragma unroll
            for (int p = 0; p < 4; ++p) {
                int row = wn + p * 16 + (lid & 7) + (((lid >> 4) & 1) << 3);
                int c = kk * 2 + ((lid >> 3) & 1);
                uint32_t bf[4];
                ldsm4(bf, s + 16384 + row * 128 + ((c ^ (row & 7)) << 4));
                #pragma unroll
                for (int mt = 0; mt < 2; ++mt) {
                    mma_f16(acc[mt][2 * p],     af[mt], bf);
                    mma_f16(acc[mt][2 * p + 1], af[mt], bf + 2);
                }
            }
        }
        __syncthreads();
        if (ch + 2 < NCH)
            load_stage(sb + (ch & 1) * STAGE_BYTES, m0, n0, M, (ch + 2) * 64, tid, A, B);
        else
            asm volatile("cp.async.commit_group;" ::: "memory");
    }

    #pragma unroll
    for (int mt = 0; mt < 2; ++mt) {
        int rbase = m0 + wm + mt * 16 + (lid >> 2);
        #pragma unroll
        for (int half = 0; half < 2; ++half) {
            int m = rbase + half * 8;
            if (m < M) {
                #pragma unroll
                for (int nt = 0; nt < 8; ++nt) {
                    int n = n0 + wn + nt * 8 + (lid & 3) * 2;
                    float2 o;
                    o.x = acc[mt][nt][half * 2 + 0] + bias[n];
                    o.y = acc[mt][nt][half * 2 + 1] + bias[n + 1];
                    if (relu) { o.x = fmaxf(o.x, 0.f); o.y = fmaxf(o.y, 0.f); }
                    if (C)
                        *reinterpret_cast<float2*>(C + (size_t)m * F + n) = o;
                    if (C16) {
                        __half2 h = __floats2half2_rn(o.x, o.y);
                        *reinterpret_cast<__half2*>(C16 + (size_t)m * F + n) = h;
                    }
                }
            }
        }
    }
}

// ==================== launcher ====================
extern "C" void kernel_launch(void* const* d_in, const int* in_sizes, int n_in,
                              void* d_out, int out_size) {
    const float* x   = (const float*)d_in[0];
    const float* W1  = (const float*)d_in[1];
    const float* b1  = (const float*)d_in[2];
    const float* W2  = (const float*)d_in[3];
    const float* b2  = (const float*)d_in[4];
    const float* W3  = (const float*)d_in[5];
    const float* b3  = (const float*)d_in[6];
    const int*   src = (const int*)d_in[7];
    const int*   dst = (const int*)d_in[8];

    float* out = (float*)d_out;
    float* h4 = out;
    float* h3 = out + (size_t)NN * F;
    float* h2 = out + 2 * (size_t)NN * F;

    void* ivec = nullptr;
    __half *x16 = nullptr, *hf16 = nullptr, *A16 = nullptr;
    __half *W1h = nullptr, *W2h = nullptr, *W3h = nullptr;
    cudaGetSymbolAddress(&ivec, g_ivec);
    cudaGetSymbolAddress((void**)&x16,  g_x16);
    cudaGetSymbolAddress((void**)&hf16, g_hf16);
    cudaGetSymbolAddress((void**)&A16,  g_A16);
    cudaGetSymbolAddress((void**)&W1h, g_W1h);
    cudaGetSymbolAddress((void**)&W2h, g_W2h);
    cudaGetSymbolAddress((void**)&W3h, g_W3h);

    cudaFuncSetAttribute(gemm_mma, cudaFuncAttributeMaxDynamicSharedMemorySize, GEMM_SMEM);

    cudaStream_t s1;
    cudaStreamCreateWithFlags(&s1, cudaStreamNonBlocking);
    cudaEvent_t evFork, evX;
    cudaEventCreateWithFlags(&evFork, cudaEventDisableTiming);
    cudaEventCreateWithFlags(&evX, cudaEventDisableTiming);

    // side stream: x->fp16 + weight transpose/quantize (overlaps CSR build)
    cudaEventRecord(evFork, 0);
    cudaStreamWaitEvent(s1, evFork, 0);
    xconvert_kernel<<<(NN * F / 4 + 255) / 256, 256, 0, s1>>>(x, x16);
    wsplit3_kernel<<<dim3(16, 16, 3), dim3(32, 32), 0, s1>>>(W1, W2, W3, W1h, W2h, W3h);
    cudaEventRecord(evX, s1);

    const int TB = 256;
    cudaMemsetAsync(ivec, 0, sizeof(int) * 3 * NN, 0);
    degree_kernel<<<(NE + TB - 1) / TB, TB>>>(src, dst);
    scan_kernel<<<1, 1024>>>();
    scatter_kernel<<<(NE + TB - 1) / TB, TB>>>(src, dst);
    cudaStreamWaitEvent(0, evX, 0);

    dim3 ggrid(4, (NN + 127) / 128);     // 4 x 79
    dim3 ggrid2(8, (NN + 127) / 128);    // dual

    // layer 1: h1 = relu(agg(x16) @ W1 + b1), fp16 only
    agg_kernel<<<NN, 128>>>(x16, A16);
    gemm_mma<<<ggrid, 256, GEMM_SMEM>>>(A16, W1h, b1, nullptr, hf16,
                                        nullptr, nullptr, nullptr, NN, 1, 0);
    // layer 2: h2 (fp32 to d_out + fp16 copy into x16)
    agg_kernel<<<NN, 128>>>(hf16, A16);
    gemm_mma<<<ggrid, 256, GEMM_SMEM>>>(A16, W2h, b2, h2, x16,
                                        nullptr, nullptr, nullptr, NN, 1, 0);
    // layer 3: shared agg feeds h3 (W2,relu) + h4 (W3) in one dual GEMM
    agg_kernel<<<NN, 128>>>(x16, A16);
    gemm_mma<<<ggrid2, 256, GEMM_SMEM>>>(A16, W2h, b2, h3, nullptr,
                                         W3h, b3, h4, NN, 1, 1);
}

// round 9
// speedup vs baseline: 5.9042x; 1.0147x over previous
#include <cuda_runtime.h>
#include <cuda_fp16.h>
#include <cstdint>

#define NN 10000
#define NE 160000
#define F 512

// ==================== scratch (device globals) ====================
__device__ int   g_ivec[3][NN];     // [0]=deg_out [1]=deg_in [2]=cnt (one memset)
#define g_deg_out (g_ivec[0])
#define g_deg_in  (g_ivec[1])
#define g_cnt     (g_ivec[2])
__device__ int   g_off[NN + 1];
__device__ int   g_bsum[40];
__device__ int   g_csr_src[NE];
__device__ float g_csr_w[NE];
__device__ __half g_x16[(size_t)NN * F];    // fp16 features: x, later h2
__device__ __half g_hf16[(size_t)NN * F];   // fp16 h1
__device__ __half g_A16[(size_t)NN * F];    // aggregated fp16 (GEMM A operand)
__device__ __half g_W1h[F * F], g_W2h[F * F], g_W3h[F * F];

// ==================== PTX helpers ====================
__device__ __forceinline__ uint32_t smem_to_u32(const void* p) {
    uint32_t a;
    asm("{ .reg .u64 t; cvta.to.shared.u64 t, %1; cvt.u32.u64 %0, t; }" : "=r"(a) : "l"(p));
    return a;
}
__device__ __forceinline__ void cp_async16(uint32_t dst, const void* src, int sz) {
    asm volatile("cp.async.cg.shared.global [%0], [%1], 16, %2;"
        :: "r"(dst), "l"(src), "r"(sz) : "memory");
}
__device__ __forceinline__ void ldsm4(uint32_t* r, uint32_t addr) {
    asm volatile("ldmatrix.sync.aligned.m8n8.x4.shared.b16 {%0,%1,%2,%3}, [%4];"
        : "=r"(r[0]), "=r"(r[1]), "=r"(r[2]), "=r"(r[3]) : "r"(addr));
}
__device__ __forceinline__ void mma_f16(float* d, const uint32_t* a, const uint32_t* b) {
    asm volatile(
        "mma.sync.aligned.m16n8k16.row.col.f32.f16.f16.f32 "
        "{%0,%1,%2,%3}, {%4,%5,%6,%7}, {%8,%9}, {%0,%1,%2,%3};"
        : "+f"(d[0]), "+f"(d[1]), "+f"(d[2]), "+f"(d[3])
        : "r"(a[0]), "r"(a[1]), "r"(a[2]), "r"(a[3]), "r"(b[0]), "r"(b[1]));
}

// ==================== setup kernels ====================
__global__ void degree_kernel(const int* __restrict__ src, const int* __restrict__ dst) {
    int e = blockIdx.x * blockDim.x + threadIdx.x;
    if (e < NE) {
        atomicAdd(&g_deg_out[src[e]], 1);
        atomicAdd(&g_deg_in[dst[e]], 1);
    }
}

// phase 1: per-block exclusive scan of deg_in (40 blocks x 256), local scans + block sums
__global__ void scan1_kernel() {
    __shared__ int wsum[8];
    int tid = threadIdx.x;
    int idx = blockIdx.x * 256 + tid;
    int v = (idx < NN) ? g_deg_in[idx] : 0;
    int x = v;
    #pragma unroll
    for (int d = 1; d < 32; d <<= 1) {
        int y = __shfl_up_sync(0xffffffffu, x, d);
        if ((tid & 31) >= d) x += y;
    }
    if ((tid & 31) == 31) wsum[tid >> 5] = x;
    __syncthreads();
    if (tid < 8) {
        int w = wsum[tid];
        #pragma unroll
        for (int d = 1; d < 8; d <<= 1) {
            int y = __shfl_up_sync(0xffu, w, d);
            if (tid >= d) w += y;
        }
        wsum[tid] = w;
    }
    __syncthreads();
    int incl = x + ((tid >= 32) ? wsum[(tid >> 5) - 1] : 0);
    if (idx <= NN) g_off[idx] = incl - v;          // local exclusive
    if (tid == 255) g_bsum[blockIdx.x] = incl;     // block total
}

// phase 2: add block prefix (each block redundantly prefixes the 40 sums)
__global__ void scan2_kernel() {
    __shared__ int pref[41];
    int tid = threadIdx.x;
    if (tid == 0) {
        int s = 0;
        #pragma unroll
        for (int b = 0; b < 40; ++b) { pref[b] = s; s += g_bsum[b]; }
        pref[40] = s;
    }
    __syncthreads();
    int idx = blockIdx.x * 256 + tid;
    if (idx < NN) g_off[idx] += pref[blockIdx.x];
    if (idx == NN - 1) g_off[NN] = pref[40];
}

__global__ void scatter_kernel(const int* __restrict__ src, const int* __restrict__ dst) {
    int e = blockIdx.x * blockDim.x + threadIdx.x;
    if (e < NE) {
        int d = dst[e];
        int pos = g_off[d] + atomicAdd(&g_cnt[d], 1);
        int s = src[e];
        g_csr_src[pos] = s;
        g_csr_w[pos]   = rsqrtf((float)g_deg_out[s]);
    }
}

// x fp32 -> fp16
__global__ void xconvert_kernel(const float* __restrict__ x, __half* __restrict__ o) {
    int i = blockIdx.x * blockDim.x + threadIdx.x;
    float4 v = reinterpret_cast<const float4*>(x)[i];
    __half2 a = __floats2half2_rn(v.x, v.y);
    __half2 b = __floats2half2_rn(v.z, v.w);
    uint32_t ua = *reinterpret_cast<uint32_t*>(&a);
    uint32_t ub = *reinterpret_cast<uint32_t*>(&b);
    reinterpret_cast<uint2*>(o)[i] = make_uint2(ua, ub);
}

// all three W k-major -> transposed fp16 Wt[n][k]
__global__ void wsplit3_kernel(const float* __restrict__ W1, const float* __restrict__ W2,
                               const float* __restrict__ W3,
                               __half* __restrict__ O1, __half* __restrict__ O2,
                               __half* __restrict__ O3) {
    const float* W = (blockIdx.z == 0) ? W1 : (blockIdx.z == 1) ? W2 : W3;
    __half* Oh = (blockIdx.z == 0) ? O1 : (blockIdx.z == 1) ? O2 : O3;
    __shared__ float t[32][33];
    int n = blockIdx.x * 32 + threadIdx.x;
    int k = blockIdx.y * 32 + threadIdx.y;
    t[threadIdx.y][threadIdx.x] = W[(size_t)k * F + n];
    __syncthreads();
    int on = blockIdx.x * 32 + threadIdx.y;
    int ok = blockIdx.y * 32 + threadIdx.x;
    Oh[(size_t)on * F + ok] = __float2half_rn(t[threadIdx.x][threadIdx.y]);
}

// ==================== aggregation (fp16 gather, fp32 accumulate, fp16 out) ====================
__global__ __launch_bounds__(128) void agg_kernel(const __half* __restrict__ x,
                                                  __half* __restrict__ o) {
    int node = blockIdx.x;
    int tid  = threadIdx.x;
    int beg = g_off[node];
    int end = g_off[node + 1];
    const uint2* x2 = reinterpret_cast<const uint2*>(x);   // row stride 128 uint2
    float4 acc = make_float4(0.f, 0.f, 0.f, 0.f);
    int i = beg;
    for (; i + 4 <= end; i += 4) {
        int   s0 = __ldg(&g_csr_src[i + 0]);
        int   s1 = __ldg(&g_csr_src[i + 1]);
        int   s2 = __ldg(&g_csr_src[i + 2]);
        int   s3 = __ldg(&g_csr_src[i + 3]);
        float w0 = __ldg(&g_csr_w[i + 0]);
        float w1 = __ldg(&g_csr_w[i + 1]);
        float w2 = __ldg(&g_csr_w[i + 2]);
        float w3 = __ldg(&g_csr_w[i + 3]);
        uint2 u0 = x2[(size_t)s0 * 128 + tid];
        uint2 u1 = x2[(size_t)s1 * 128 + tid];
        uint2 u2 = x2[(size_t)s2 * 128 + tid];
        uint2 u3 = x2[(size_t)s3 * 128 + tid];
        float2 a0 = __half22float2(*reinterpret_cast<__half2*>(&u0.x));
        float2 b0 = __half22float2(*reinterpret_cast<__half2*>(&u0.y));
        float2 a1 = __half22float2(*reinterpret_cast<__half2*>(&u1.x));
        float2 b1 = __half22float2(*reinterpret_cast<__half2*>(&u1.y));
        float2 a2 = __half22float2(*reinterpret_cast<__half2*>(&u2.x));
        float2 b2 = __half22float2(*reinterpret_cast<__half2*>(&u2.y));
        float2 a3 = __half22float2(*reinterpret_cast<__half2*>(&u3.x));
        float2 b3 = __half22float2(*reinterpret_cast<__half2*>(&u3.y));
        acc.x = fmaf(w0, a0.x, acc.x); acc.y = fmaf(w0, a0.y, acc.y);
        acc.z = fmaf(w0, b0.x, acc.z); acc.w = fmaf(w0, b0.y, acc.w);
        acc.x = fmaf(w1, a1.x, acc.x); acc.y = fmaf(w1, a1.y, acc.y);
        acc.z = fmaf(w1, b1.x, acc.z); acc.w = fmaf(w1, b1.y, acc.w);
        acc.x = fmaf(w2, a2.x, acc.x); acc.y = fmaf(w2, a2.y, acc.y);
        acc.z = fmaf(w2, b2.x, acc.z); acc.w = fmaf(w2, b2.y, acc.w);
        acc.x = fmaf(w3, a3.x, acc.x); acc.y = fmaf(w3, a3.y, acc.y);
        acc.z = fmaf(w3, b3.x, acc.z); acc.w = fmaf(w3, b3.y, acc.w);
    }
    for (; i < end; ++i) {
        int   s = __ldg(&g_csr_src[i]);
        float w = __ldg(&g_csr_w[i]);
        uint2 u = x2[(size_t)s * 128 + tid];
        float2 a = __half22float2(*reinterpret_cast<__half2*>(&u.x));
        float2 b = __half22float2(*reinterpret_cast<__half2*>(&u.y));
        acc.x = fmaf(w, a.x, acc.x); acc.y = fmaf(w, a.y, acc.y);
        acc.z = fmaf(w, b.x, acc.z); acc.w = fmaf(w, b.y, acc.w);
    }
    float ni = (end > beg) ? rsqrtf((float)(end - beg)) : 0.f;
    __half2 p0 = __floats2half2_rn(acc.x * ni, acc.y * ni);
    __half2 p1 = __floats2half2_rn(acc.z * ni, acc.w * ni);
    uint2 u = make_uint2(*reinterpret_cast<uint32_t*>(&p0), *reinterpret_cast<uint32_t*>(&p1));
    reinterpret_cast<uint2*>(o + (size_t)node * F)[tid] = u;
}

// ==================== mma.sync GEMM: C = A@B^T + bias (3-stage pipeline) ====================
// CTA 128x128, 256 thr (8 warps, warp tile 32x64), BK=64, 3 stages.
// Stage (32KB): A[0,16K) B[16K,32K). Rows 128B, 16B chunk c at row r -> c^(r&7).
#define STAGE_BYTES 32768
#define NSTAGE 3
#define GEMM_SMEM (NSTAGE * STAGE_BYTES)

__device__ __forceinline__ void load_stage(
    uint32_t s, int m0, int n0, int M, int k0, int tid,
    const __half* __restrict__ A, const __half* __restrict__ B)
{
    #pragma unroll
    for (int i = 0; i < 4; ++i) {
        int v = tid + i * 256;        // 0..1023
        int row = v >> 3, c = v & 7;
        uint32_t phys = (uint32_t)(row * 128 + ((c ^ (row & 7)) << 4));
        size_t gA = (size_t)(m0 + row) * F + k0 + c * 8;
        int sz = (m0 + row < M) ? 16 : 0;
        cp_async16(s + phys, A + gA, sz);
        size_t gB = (size_t)(n0 + row) * F + k0 + c * 8;
        cp_async16(s + 16384 + phys, B + gB, 16);
    }
    asm volatile("cp.async.commit_group;" ::: "memory");
}

// dual=0: grid.x=4; dual=1: grid.x=8, high 4 -> (B2,bias2,C2,no relu)
__global__ __launch_bounds__(256, 2) void gemm_mma(
    const __half* __restrict__ A,
    const __half* __restrict__ B, const float* __restrict__ bias,
    float* __restrict__ C, __half* __restrict__ C16,
    const __half* __restrict__ B2, const float* __restrict__ bias2, float* __restrict__ C2,
    int M, int relu, int dual)
{
    extern __shared__ char smem[];
    const uint32_t sb = smem_to_u32(smem);
    const int tid = threadIdx.x;
    const int wid = tid >> 5, lid = tid & 31;
    int nb = blockIdx.x;
    if (dual && nb >= 4) {
        nb -= 4;
        B = B2; bias = bias2; C = C2; C16 = nullptr; relu = 0;
    }
    const int m0 = blockIdx.y * 128, n0 = nb * 128;
    const int wm = (wid & 3) * 32;
    const int wn = (wid >> 2) * 64;

    float acc[2][8][4];
    #pragma unroll
    for (int a = 0; a < 2; ++a)
        #pragma unroll
        for (int b = 0; b < 8; ++b)
            #pragma unroll
            for (int c = 0; c < 4; ++c) acc[a][b][c] = 0.f;

    load_stage(sb, m0, n0, M, 0, tid, A, B);
    load_stage(sb + STAGE_BYTES, m0, n0, M, 64, tid, A, B);

    const int NCH = F / 64;   // 8
    for (int ch = 0; ch < NCH; ++ch) {
        asm volatile("cp.async.wait_group 1;" ::: "memory");   // chunk ch resident
        __syncthreads();
        // prefetch chunk ch+2 into the stage freed at the last sync
        if (ch + 2 < NCH)
            load_stage(sb + ((ch + 2) % NSTAGE) * STAGE_BYTES, m0, n0, M, (ch + 2) * 64, tid, A, B);
        else
            asm volatile("cp.async.commit_group;" ::: "memory");

        const uint32_t s = sb + (ch % NSTAGE) * STAGE_BYTES;
        #pragma unroll
        for (int kk = 0; kk < 4; ++kk) {
            uint32_t af[2][4];
            #pragma unroll
            for (int mt = 0; mt < 2; ++mt) {
                int row = wm + mt * 16 + (lid & 15);
                int c = kk * 2 + ((lid >> 4) & 1);
                ldsm4(af[mt], s + row * 128 + ((c ^ (row & 7)) << 4));
            }
            #pragma unroll
            for (int p = 0; p < 4; ++p) {
                int row = wn + p * 16 + (lid & 7) + (((lid >> 4) & 1) << 3);
                int c = kk * 2 + ((lid >> 3) & 1);
                uint32_t bf[4];
                ldsm4(bf, s + 16384 + row * 128 + ((c ^ (row & 7)) << 4));
                #pragma unroll
                for (int mt = 0; mt < 2; ++mt) {
                    mma_f16(acc[mt][2 * p],     af[mt], bf);
                    mma_f16(acc[mt][2 * p + 1], af[mt], bf + 2);
                }
            }
        }
        __syncthreads();   // all warps done with stage (ch%3) before it is refilled
    }

    #pragma unroll
    for (int mt = 0; mt < 2; ++mt) {
        int rbase = m0 + wm + mt * 16 + (lid >> 2);
        #pragma unroll
        for (int half = 0; half < 2; ++half) {
            int m = rbase + half * 8;
            if (m < M) {
                #pragma unroll
                for (int nt = 0; nt < 8; ++nt) {
                    int n = n0 + wn + nt * 8 + (lid & 3) * 2;
                    float2 o;
                    o.x = acc[mt][nt][half * 2 + 0] + bias[n];
                    o.y = acc[mt][nt][half * 2 + 1] + bias[n + 1];
                    if (relu) { o.x = fmaxf(o.x, 0.f); o.y = fmaxf(o.y, 0.f); }
                    if (C)
                        *reinterpret_cast<float2*>(C + (size_t)m * F + n) = o;
                    if (C16) {
                        __half2 h = __floats2half2_rn(o.x, o.y);
                        *reinterpret_cast<__half2*>(C16 + (size_t)m * F + n) = h;
                    }
                }
            }
        }
    }
}

// ==================== launcher ====================
extern "C" void kernel_launch(void* const* d_in, const int* in_sizes, int n_in,
                              void* d_out, int out_size) {
    const float* x   = (const float*)d_in[0];
    const float* W1  = (const float*)d_in[1];
    const float* b1  = (const float*)d_in[2];
    const float* W2  = (const float*)d_in[3];
    const float* b2  = (const float*)d_in[4];
    const float* W3  = (const float*)d_in[5];
    const float* b3  = (const float*)d_in[6];
    const int*   src = (const int*)d_in[7];
    const int*   dst = (const int*)d_in[8];

    float* out = (float*)d_out;
    float* h4 = out;
    float* h3 = out + (size_t)NN * F;
    float* h2 = out + 2 * (size_t)NN * F;

    void* ivec = nullptr;
    __half *x16 = nullptr, *hf16 = nullptr, *A16 = nullptr;
    __half *W1h = nullptr, *W2h = nullptr, *W3h = nullptr;
    cudaGetSymbolAddress(&ivec, g_ivec);
    cudaGetSymbolAddress((void**)&x16,  g_x16);
    cudaGetSymbolAddress((void**)&hf16, g_hf16);
    cudaGetSymbolAddress((void**)&A16,  g_A16);
    cudaGetSymbolAddress((void**)&W1h, g_W1h);
    cudaGetSymbolAddress((void**)&W2h, g_W2h);
    cudaGetSymbolAddress((void**)&W3h, g_W3h);

    cudaFuncSetAttribute(gemm_mma, cudaFuncAttributeMaxDynamicSharedMemorySize, GEMM_SMEM);

    cudaStream_t s1;
    cudaStreamCreateWithFlags(&s1, cudaStreamNonBlocking);
    cudaEvent_t evFork, evX;
    cudaEventCreateWithFlags(&evFork, cudaEventDisableTiming);
    cudaEventCreateWithFlags(&evX, cudaEventDisableTiming);

    // side stream: x->fp16 + weight transpose/quantize (overlaps CSR build)
    cudaEventRecord(evFork, 0);
    cudaStreamWaitEvent(s1, evFork, 0);
    xconvert_kernel<<<(NN * F / 4 + 255) / 256, 256, 0, s1>>>(x, x16);
    wsplit3_kernel<<<dim3(16, 16, 3), dim3(32, 32), 0, s1>>>(W1, W2, W3, W1h, W2h, W3h);
    cudaEventRecord(evX, s1);

    const int TB = 256;
    cudaMemsetAsync(ivec, 0, sizeof(int) * 3 * NN, 0);
    degree_kernel<<<(NE + TB - 1) / TB, TB>>>(src, dst);
    scan1_kernel<<<40, 256>>>();
    scan2_kernel<<<40, 256>>>();
    scatter_kernel<<<(NE + TB - 1) / TB, TB>>>(src, dst);
    cudaStreamWaitEvent(0, evX, 0);

    dim3 ggrid(4, (NN + 127) / 128);     // 4 x 79
    dim3 ggrid2(8, (NN + 127) / 128);    // dual

    // layer 1: h1 = relu(agg(x16) @ W1 + b1), fp16 only
    agg_kernel<<<NN, 128>>>(x16, A16);
    gemm_mma<<<ggrid, 256, GEMM_SMEM>>>(A16, W1h, b1, nullptr, hf16,
                                        nullptr, nullptr, nullptr, NN, 1, 0);
    // layer 2: h2 (fp32 to d_out + fp16 copy into x16)
    agg_kernel<<<NN, 128>>>(hf16, A16);
    gemm_mma<<<ggrid, 256, GEMM_SMEM>>>(A16, W2h, b2, h2, x16,
                                        nullptr, nullptr, nullptr, NN, 1, 0);
    // layer 3: shared agg feeds h3 (W2,relu) + h4 (W3) in one dual GEMM
    agg_kernel<<<NN, 128>>>(x16, A16);
    gemm_mma<<<ggrid2, 256, GEMM_SMEM>>>(A16, W2h, b2, h3, nullptr,
                                         W3h, b3, h4, NN, 1, 1);
}

// round 10
// speedup vs baseline: 6.0573x; 1.0259x over previous
#include <cuda_runtime.h>
#include <cuda_fp16.h>
#include <cstdint>

#define NN 10000
#define NE 160000
#define F 512

// ==================== scratch (device globals) ====================
__device__ int   g_ivec[3][NN];     // [0]=deg_out [1]=deg_in [2]=cnt (one memset)
#define g_deg_out (g_ivec[0])
#define g_deg_in  (g_ivec[1])
#define g_cnt     (g_ivec[2])
__device__ int   g_off[NN + 1];
__device__ int   g_bsum[40];
__device__ int   g_csr_src[NE];
__device__ float g_csr_w[NE];
__device__ __half g_x16[(size_t)NN * F];    // fp16 x, later fp16 h2
__device__ __half g_hf16[(size_t)NN * F];   // fp16 h1
__device__ __half g_A16[(size_t)NN * F];    // Y1, then aggregated GEMM A operand
__device__ __half g_W1h[F * F], g_W2h[F * F], g_W3h[F * F];

// ==================== PTX helpers ====================
__device__ __forceinline__ uint32_t smem_to_u32(const void* p) {
    uint32_t a;
    asm("{ .reg .u64 t; cvta.to.shared.u64 t, %1; cvt.u32.u64 %0, t; }" : "=r"(a) : "l"(p));
    return a;
}
__device__ __forceinline__ void cp_async16(uint32_t dst, const void* src, int sz) {
    asm volatile("cp.async.cg.shared.global [%0], [%1], 16, %2;"
        :: "r"(dst), "l"(src), "r"(sz) : "memory");
}
__device__ __forceinline__ void ldsm4(uint32_t* r, uint32_t addr) {
    asm volatile("ldmatrix.sync.aligned.m8n8.x4.shared.b16 {%0,%1,%2,%3}, [%4];"
        : "=r"(r[0]), "=r"(r[1]), "=r"(r[2]), "=r"(r[3]) : "r"(addr));
}
__device__ __forceinline__ void mma_f16(float* d, const uint32_t* a, const uint32_t* b) {
    asm volatile(
        "mma.sync.aligned.m16n8k16.row.col.f32.f16.f16.f32 "
        "{%0,%1,%2,%3}, {%4,%5,%6,%7}, {%8,%9}, {%0,%1,%2,%3};"
        : "+f"(d[0]), "+f"(d[1]), "+f"(d[2]), "+f"(d[3])
        : "r"(a[0]), "r"(a[1]), "r"(a[2]), "r"(a[3]), "r"(b[0]), "r"(b[1]));
}

// ==================== setup kernels ====================
__global__ void degree_kernel(const int* __restrict__ src, const int* __restrict__ dst) {
    int e = blockIdx.x * blockDim.x + threadIdx.x;
    if (e < NE) {
        atomicAdd(&g_deg_out[src[e]], 1);
        atomicAdd(&g_deg_in[dst[e]], 1);
    }
}

// phase 1: per-block exclusive scan of deg_in (40 blocks x 256)
__global__ void scan1_kernel() {
    __shared__ int wsum[8];
    int tid = threadIdx.x;
    int idx = blockIdx.x * 256 + tid;
    int v = (idx < NN) ? g_deg_in[idx] : 0;
    int x = v;
    #pragma unroll
    for (int d = 1; d < 32; d <<= 1) {
        int y = __shfl_up_sync(0xffffffffu, x, d);
        if ((tid & 31) >= d) x += y;
    }
    if ((tid & 31) == 31) wsum[tid >> 5] = x;
    __syncthreads();
    if (tid < 8) {
        int w = wsum[tid];
        #pragma unroll
        for (int d = 1; d < 8; d <<= 1) {
            int y = __shfl_up_sync(0xffu, w, d);
            if (tid >= d) w += y;
        }
        wsum[tid] = w;
    }
    __syncthreads();
    int incl = x + ((tid >= 32) ? wsum[(tid >> 5) - 1] : 0);
    if (idx <= NN) g_off[idx] = incl - v;
    if (tid == 255) g_bsum[blockIdx.x] = incl;
}

// phase 2: add block prefix
__global__ void scan2_kernel() {
    __shared__ int pref[41];
    int tid = threadIdx.x;
    if (tid == 0) {
        int s = 0;
        #pragma unroll
        for (int b = 0; b < 40; ++b) { pref[b] = s; s += g_bsum[b]; }
        pref[40] = s;
    }
    __syncthreads();
    int idx = blockIdx.x * 256 + tid;
    if (idx < NN) g_off[idx] += pref[blockIdx.x];
    if (idx == NN - 1) g_off[NN] = pref[40];
}

__global__ void scatter_kernel(const int* __restrict__ src, const int* __restrict__ dst) {
    int e = blockIdx.x * blockDim.x + threadIdx.x;
    if (e < NE) {
        int d = dst[e];
        int pos = g_off[d] + atomicAdd(&g_cnt[d], 1);
        int s = src[e];
        g_csr_src[pos] = s;
        g_csr_w[pos]   = rsqrtf((float)g_deg_out[s]);
    }
}

// x fp32 -> fp16
__global__ void xconvert_kernel(const float* __restrict__ x, __half* __restrict__ o) {
    int i = blockIdx.x * blockDim.x + threadIdx.x;
    float4 v = reinterpret_cast<const float4*>(x)[i];
    __half2 a = __floats2half2_rn(v.x, v.y);
    __half2 b = __floats2half2_rn(v.z, v.w);
    uint32_t ua = *reinterpret_cast<uint32_t*>(&a);
    uint32_t ub = *reinterpret_cast<uint32_t*>(&b);
    reinterpret_cast<uint2*>(o)[i] = make_uint2(ua, ub);
}

// all three W k-major -> transposed fp16 Wt[n][k]
__global__ void wsplit3_kernel(const float* __restrict__ W1, const float* __restrict__ W2,
                               const float* __restrict__ W3,
                               __half* __restrict__ O1, __half* __restrict__ O2,
                               __half* __restrict__ O3) {
    const float* W = (blockIdx.z == 0) ? W1 : (blockIdx.z == 1) ? W2 : W3;
    __half* Oh = (blockIdx.z == 0) ? O1 : (blockIdx.z == 1) ? O2 : O3;
    __shared__ float t[32][33];
    int n = blockIdx.x * 32 + threadIdx.x;
    int k = blockIdx.y * 32 + threadIdx.y;
    t[threadIdx.y][threadIdx.x] = W[(size_t)k * F + n];
    __syncthreads();
    int on = blockIdx.x * 32 + threadIdx.y;
    int ok = blockIdx.y * 32 + threadIdx.x;
    Oh[(size_t)on * F + ok] = __float2half_rn(t[threadIdx.x][threadIdx.y]);
}

// ==================== aggregation (fp16 gather, fp32 acc, optional bias+relu) ====================
__global__ __launch_bounds__(128) void agg_kernel(const __half* __restrict__ x,
                                                  __half* __restrict__ o,
                                                  const float* __restrict__ bias,
                                                  int relu) {
    int node = blockIdx.x;
    int tid  = threadIdx.x;
    int beg = g_off[node];
    int end = g_off[node + 1];
    const uint2* x2 = reinterpret_cast<const uint2*>(x);   // row stride 128 uint2
    float4 acc = make_float4(0.f, 0.f, 0.f, 0.f);
    int i = beg;
    for (; i + 4 <= end; i += 4) {
        int   s0 = __ldg(&g_csr_src[i + 0]);
        int   s1 = __ldg(&g_csr_src[i + 1]);
        int   s2 = __ldg(&g_csr_src[i + 2]);
        int   s3 = __ldg(&g_csr_src[i + 3]);
        float w0 = __ldg(&g_csr_w[i + 0]);
        float w1 = __ldg(&g_csr_w[i + 1]);
        float w2 = __ldg(&g_csr_w[i + 2]);
        float w3 = __ldg(&g_csr_w[i + 3]);
        uint2 u0 = x2[(size_t)s0 * 128 + tid];
        uint2 u1 = x2[(size_t)s1 * 128 + tid];
        uint2 u2 = x2[(size_t)s2 * 128 + tid];
        uint2 u3 = x2[(size_t)s3 * 128 + tid];
        float2 a0 = __half22float2(*reinterpret_cast<__half2*>(&u0.x));
        float2 b0 = __half22float2(*reinterpret_cast<__half2*>(&u0.y));
        float2 a1 = __half22float2(*reinterpret_cast<__half2*>(&u1.x));
        float2 b1 = __half22float2(*reinterpret_cast<__half2*>(&u1.y));
        float2 a2 = __half22float2(*reinterpret_cast<__half2*>(&u2.x));
        float2 b2 = __half22float2(*reinterpret_cast<__half2*>(&u2.y));
        float2 a3 = __half22float2(*reinterpret_cast<__half2*>(&u3.x));
        float2 b3 = __half22float2(*reinterpret_cast<__half2*>(&u3.y));
        acc.x = fmaf(w0, a0.x, acc.x); acc.y = fmaf(w0, a0.y, acc.y);
        acc.z = fmaf(w0, b0.x, acc.z); acc.w = fmaf(w0, b0.y, acc.w);
        acc.x = fmaf(w1, a1.x, acc.x); acc.y = fmaf(w1, a1.y, acc.y);
        acc.z = fmaf(w1, b1.x, acc.z); acc.w = fmaf(w1, b1.y, acc.w);
        acc.x = fmaf(w2, a2.x, acc.x); acc.y = fmaf(w2, a2.y, acc.y);
        acc.z = fmaf(w2, b2.x, acc.z); acc.w = fmaf(w2, b2.y, acc.w);
        acc.x = fmaf(w3, a3.x, acc.x); acc.y = fmaf(w3, a3.y, acc.y);
        acc.z = fmaf(w3, b3.x, acc.z); acc.w = fmaf(w3, b3.y, acc.w);
    }
    for (; i < end; ++i) {
        int   s = __ldg(&g_csr_src[i]);
        float w = __ldg(&g_csr_w[i]);
        uint2 u = x2[(size_t)s * 128 + tid];
        float2 a = __half22float2(*reinterpret_cast<__half2*>(&u.x));
        float2 b = __half22float2(*reinterpret_cast<__half2*>(&u.y));
        acc.x = fmaf(w, a.x, acc.x); acc.y = fmaf(w, a.y, acc.y);
        acc.z = fmaf(w, b.x, acc.z); acc.w = fmaf(w, b.y, acc.w);
    }
    float ni = (end > beg) ? rsqrtf((float)(end - beg)) : 0.f;
    float r0 = acc.x * ni, r1 = acc.y * ni, r2 = acc.z * ni, r3 = acc.w * ni;
    if (bias) {
        float4 bv = reinterpret_cast<const float4*>(bias)[tid];
        r0 += bv.x; r1 += bv.y; r2 += bv.z; r3 += bv.w;
    }
    if (relu) {
        r0 = fmaxf(r0, 0.f); r1 = fmaxf(r1, 0.f);
        r2 = fmaxf(r2, 0.f); r3 = fmaxf(r3, 0.f);
    }
    __half2 p0 = __floats2half2_rn(r0, r1);
    __half2 p1 = __floats2half2_rn(r2, r3);
    uint2 u = make_uint2(*reinterpret_cast<uint32_t*>(&p0), *reinterpret_cast<uint32_t*>(&p1));
    reinterpret_cast<uint2*>(o + (size_t)node * F)[tid] = u;
}

// ==================== mma.sync GEMM: C = A@B^T (+bias, +relu) ====================
// CTA 128x128, 256 thr (warp tile 32x64), BK=64, 3 stages, 2 CTAs/SM.
#define STAGE_BYTES 32768
#define NSTAGE 3
#define GEMM_SMEM (NSTAGE * STAGE_BYTES)

__device__ __forceinline__ void load_stage(
    uint32_t s, int m0, int n0, int M, int k0, int tid,
    const __half* __restrict__ A, const __half* __restrict__ B)
{
    #pragma unroll
    for (int i = 0; i < 4; ++i) {
        int v = tid + i * 256;
        int row = v >> 3, c = v & 7;
        uint32_t phys = (uint32_t)(row * 128 + ((c ^ (row & 7)) << 4));
        size_t gA = (size_t)(m0 + row) * F + k0 + c * 8;
        int sz = (m0 + row < M) ? 16 : 0;
        cp_async16(s + phys, A + gA, sz);
        size_t gB = (size_t)(n0 + row) * F + k0 + c * 8;
        cp_async16(s + 16384 + phys, B + gB, 16);
    }
    asm volatile("cp.async.commit_group;" ::: "memory");
}

__global__ __launch_bounds__(256, 2) void gemm_mma(
    const __half* __restrict__ A,
    const __half* __restrict__ B, const float* __restrict__ bias,
    float* __restrict__ C, __half* __restrict__ C16,
    const __half* __restrict__ B2, const float* __restrict__ bias2, float* __restrict__ C2,
    int M, int relu, int dual)
{
    extern __shared__ char smem[];
    const uint32_t sb = smem_to_u32(smem);
    const int tid = threadIdx.x;
    const int wid = tid >> 5, lid = tid & 31;
    int nb = blockIdx.x;
    if (dual && nb >= 4) {
        nb -= 4;
        B = B2; bias = bias2; C = C2; C16 = nullptr; relu = 0;
    }
    const int m0 = blockIdx.y * 128, n0 = nb * 128;
    const int wm = (wid & 3) * 32;
    const int wn = (wid >> 2) * 64;

    float acc[2][8][4];
    #pragma unroll
    for (int a = 0; a < 2; ++a)
        #pragma unroll
        for (int b = 0; b < 8; ++b)
            #pragma unroll
            for (int c = 0; c < 4; ++c) acc[a][b][c] = 0.f;

    load_stage(sb, m0, n0, M, 0, tid, A, B);
    load_stage(sb + STAGE_BYTES, m0, n0, M, 64, tid, A, B);

    const int NCH = F / 64;   // 8
    for (int ch = 0; ch < NCH; ++ch) {
        asm volatile("cp.async.wait_group 1;" ::: "memory");
        __syncthreads();
        if (ch + 2 < NCH)
            load_stage(sb + ((ch + 2) % NSTAGE) * STAGE_BYTES, m0, n0, M, (ch + 2) * 64, tid, A, B);
        else
            asm volatile("cp.async.commit_group;" ::: "memory");

        const uint32_t s = sb + (ch % NSTAGE) * STAGE_BYTES;
        #pragma unroll
        for (int kk = 0; kk < 4; ++kk) {
            uint32_t af[2][4];
            #pragma unroll
            for (int mt = 0; mt < 2; ++mt) {
                int row = wm + mt * 16 + (lid & 15);
                int c = kk * 2 + ((lid >> 4) & 1);
                ldsm4(af[mt], s + row * 128 + ((c ^ (row & 7)) << 4));
            }
            #pragma unroll
            for (int p = 0; p < 4; ++p) {
                int row = wn + p * 16 + (lid & 7) + (((lid >> 4) & 1) << 3);
                int c = kk * 2 + ((lid >> 3) & 1);
                uint32_t bf[4];
                ldsm4(bf, s + 16384 + row * 128 + ((c ^ (row & 7)) << 4));
                #pragma unroll
                for (int mt = 0; mt < 2; ++mt) {
                    mma_f16(acc[mt][2 * p],     af[mt], bf);
                    mma_f16(acc[mt][2 * p + 1], af[mt], bf + 2);
                }
            }
        }
        __syncthreads();
    }

    #pragma unroll
    for (int mt = 0; mt < 2; ++mt) {
        int rbase = m0 + wm + mt * 16 + (lid >> 2);
        #pragma unroll
        for (int half = 0; half < 2; ++half) {
            int m = rbase + half * 8;
            if (m < M) {
                #pragma unroll
                for (int nt = 0; nt < 8; ++nt) {
                    int n = n0 + wn + nt * 8 + (lid & 3) * 2;
                    float2 o;
                    o.x = acc[mt][nt][half * 2 + 0];
                    o.y = acc[mt][nt][half * 2 + 1];
                    if (bias) { o.x += bias[n]; o.y += bias[n + 1]; }
                    if (relu) { o.x = fmaxf(o.x, 0.f); o.y = fmaxf(o.y, 0.f); }
                    if (C)
                        *reinterpret_cast<float2*>(C + (size_t)m * F + n) = o;
                    if (C16) {
                        __half2 h = __floats2half2_rn(o.x, o.y);
                        *reinterpret_cast<__half2*>(C16 + (size_t)m * F + n) = h;
                    }
                }
            }
        }
    }
}

// ==================== launcher ====================
extern "C" void kernel_launch(void* const* d_in, const int* in_sizes, int n_in,
                              void* d_out, int out_size) {
    const float* x   = (const float*)d_in[0];
    const float* W1  = (const float*)d_in[1];
    const float* b1  = (const float*)d_in[2];
    const float* W2  = (const float*)d_in[3];
    const float* b2  = (const float*)d_in[4];
    const float* W3  = (const float*)d_in[5];
    const float* b3  = (const float*)d_in[6];
    const int*   src = (const int*)d_in[7];
    const int*   dst = (const int*)d_in[8];

    float* out = (float*)d_out;
    float* h4 = out;
    float* h3 = out + (size_t)NN * F;
    float* h2 = out + 2 * (size_t)NN * F;

    void* ivec = nullptr;
    __half *x16 = nullptr, *hf16 = nullptr, *A16 = nullptr;
    __half *W1h = nullptr, *W2h = nullptr, *W3h = nullptr;
    cudaGetSymbolAddress(&ivec, g_ivec);
    cudaGetSymbolAddress((void**)&x16,  g_x16);
    cudaGetSymbolAddress((void**)&hf16, g_hf16);
    cudaGetSymbolAddress((void**)&A16,  g_A16);
    cudaGetSymbolAddress((void**)&W1h, g_W1h);
    cudaGetSymbolAddress((void**)&W2h, g_W2h);
    cudaGetSymbolAddress((void**)&W3h, g_W3h);

    cudaFuncSetAttribute(gemm_mma, cudaFuncAttributeMaxDynamicSharedMemorySize, GEMM_SMEM);

    cudaStream_t s1;
    cudaStreamCreateWithFlags(&s1, cudaStreamNonBlocking);
    cudaEvent_t evFork, evY1;
    cudaEventCreateWithFlags(&evFork, cudaEventDisableTiming);
    cudaEventCreateWithFlags(&evY1, cudaEventDisableTiming);

    const int TB = 256;
    dim3 ggrid(4, (NN + 127) / 128);
    dim3 ggrid2(8, (NN + 127) / 128);

    // ---- side stream: x->fp16, weights, and Y1 = x16 @ W1 (CSR-independent!) ----
    cudaEventRecord(evFork, 0);
    cudaStreamWaitEvent(s1, evFork, 0);
    xconvert_kernel<<<(NN * F / 4 + 255) / 256, 256, 0, s1>>>(x, x16);
    wsplit3_kernel<<<dim3(16, 16, 3), dim3(32, 32), 0, s1>>>(W1, W2, W3, W1h, W2h, W3h);
    gemm_mma<<<ggrid, 256, GEMM_SMEM, s1>>>(x16, W1h, nullptr, nullptr, A16,
                                            nullptr, nullptr, nullptr, NN, 0, 0);
    cudaEventRecord(evY1, s1);

    // ---- main stream: CSR build (overlaps the side stream) ----
    cudaMemsetAsync(ivec, 0, sizeof(int) * 3 * NN, 0);
    degree_kernel<<<(NE + TB - 1) / TB, TB>>>(src, dst);
    scan1_kernel<<<40, 256>>>();
    scan2_kernel<<<40, 256>>>();
    scatter_kernel<<<(NE + TB - 1) / TB, TB>>>(src, dst);
    cudaStreamWaitEvent(0, evY1, 0);

    // layer 1: h1 = relu(Agg(Y1) + b1)      [linearity: Agg(X)W1 = Agg(X W1)]
    agg_kernel<<<NN, 128>>>(A16, hf16, b1, 1);
    // layer 2: h2 = relu(Agg(h1) W2 + b2)   -> fp32 d_out + fp16 x16
    agg_kernel<<<NN, 128>>>(hf16, A16, nullptr, 0);
    gemm_mma<<<ggrid, 256, GEMM_SMEM>>>(A16, W2h, b2, h2, x16,
                                        nullptr, nullptr, nullptr, NN, 1, 0);
    // layer 3: shared agg feeds h3 (W2,relu) + h4 (W3) in one dual GEMM
    agg_kernel<<<NN, 128>>>(x16, A16, nullptr, 0);
    gemm_mma<<<ggrid2, 256, GEMM_SMEM>>>(A16, W2h, b2, h3, nullptr,
                                         W3h, b3, h4, NN, 1, 1);
}